// round 7
// baseline (speedup 1.0000x reference)
#include <cuda_runtime.h>
#include <cstdint>

// NonLocalBlock B=8, N=4096, M=2048, C=256, d=128
#define NB 8
#define NN 4096
#define NM 2048
#define NC 256
#define ND 128

__device__ float g_theta[NB * NN * ND];
__device__ float g_phi  [NB * NN * ND];
__device__ float g_gg   [NB * NN * ND];
__device__ float g_phiP [NB * NM * ND];          // [b][m][d]
__device__ float g_gPt  [NB * ND * NM];          // [b][d][m]
__device__ float g_y    [NB * NN * ND];

// ---------------------------------------------------------------------------
__device__ __forceinline__ uint32_t f2tf32(float v) {
    uint32_t r;
    asm("cvt.rna.tf32.f32 %0, %1;" : "=r"(r) : "f"(v));
    return r;
}
__device__ __forceinline__ void mma_tf32(float (&d)[4],
                                         uint32_t a0, uint32_t a1, uint32_t a2, uint32_t a3,
                                         uint32_t b0, uint32_t b1) {
    asm volatile(
        "mma.sync.aligned.m16n8k8.row.col.f32.tf32.tf32.f32 "
        "{%0,%1,%2,%3}, {%4,%5,%6,%7}, {%8,%9}, {%0,%1,%2,%3};"
        : "+f"(d[0]), "+f"(d[1]), "+f"(d[2]), "+f"(d[3])
        : "r"(a0), "r"(a1), "r"(a2), "r"(a3), "r"(b0), "r"(b1));
}

#define TS 68   // k-chunk tile stride (rows x 64 used cols)

// ---------------------------------------------------------------------------
// Projection GEMM (HMMA 3xTF32): C[32768,128] = x[32768,256] @ W[256,128], x3
// Block 128 rows x 128 cols; 8 warps (4x2), warp tile 32x64; K in 4 chunks.
// smem: As 128xTS (x rows), Bs 128xTS (W^T: n-major)
// ---------------------------------------------------------------------------
__global__ __launch_bounds__(256, 2) void proj_kernel(
    const float* __restrict__ x, const float* __restrict__ Wt,
    const float* __restrict__ Wp, const float* __restrict__ Wg)
{
    extern __shared__ float sm[];
    float* As = sm;              // 128 x TS
    float* Bs = sm + 128 * TS;   // 128 x TS (row = n, col = k)

    const float* W; float* out;
    if (blockIdx.z == 0)      { W = Wt; out = g_theta; }
    else if (blockIdx.z == 1) { W = Wp; out = g_phi; }
    else                      { W = Wg; out = g_gg; }

    int tid = threadIdx.x, row0 = blockIdx.x * 128;
    int lane = tid & 31, g = lane >> 2, t = lane & 3;
    int wid = tid >> 5, wr = wid >> 1, wc = wid & 1;
    int r0 = wr * 32, c0 = wc * 64;

    float acc[2][8][4];
#pragma unroll
    for (int mt = 0; mt < 2; mt++)
#pragma unroll
        for (int nt = 0; nt < 8; nt++)
#pragma unroll
            for (int i = 0; i < 4; i++) acc[mt][nt][i] = 0.f;

#pragma unroll 1
    for (int kc = 0; kc < 4; kc++) {
        int k0 = kc * 64;
        __syncthreads();
        // A: 128 rows x 64 k  (coalesced float4)
#pragma unroll
        for (int q = 0; q < 8; q++) {
            int li = q * 256 + tid, r = li >> 4, c = (li & 15) * 4;
            *(float4*)&As[r * TS + c] = *(const float4*)(x + (size_t)(row0 + r) * NC + k0 + c);
        }
        // B: W[k][n] -> Bs[n][k]; thread loads 4 consecutive k for one n
#pragma unroll
        for (int q = 0; q < 8; q++) {
            int li = q * 256 + tid, n = li & 127, kq = li >> 7;
            float4 v;
            v.x = W[(size_t)(k0 + kq * 4 + 0) * ND + n];
            v.y = W[(size_t)(k0 + kq * 4 + 1) * ND + n];
            v.z = W[(size_t)(k0 + kq * 4 + 2) * ND + n];
            v.w = W[(size_t)(k0 + kq * 4 + 3) * ND + n];
            *(float4*)&Bs[n * TS + kq * 4] = v;
        }
        __syncthreads();
#pragma unroll 2
        for (int kst = 0; kst < 8; kst++) {
            int kk = kst * 8;
            uint32_t ah[2][4], al[2][4];
#pragma unroll
            for (int mt = 0; mt < 2; mt++) {
                const float* ab = As + (r0 + 16 * mt + g) * TS + kk + t;
                float v0 = ab[0], v1 = ab[8 * TS], v2 = ab[4], v3 = ab[8 * TS + 4];
                ah[mt][0] = f2tf32(v0); al[mt][0] = f2tf32(v0 - __uint_as_float(ah[mt][0]));
                ah[mt][1] = f2tf32(v1); al[mt][1] = f2tf32(v1 - __uint_as_float(ah[mt][1]));
                ah[mt][2] = f2tf32(v2); al[mt][2] = f2tf32(v2 - __uint_as_float(ah[mt][2]));
                ah[mt][3] = f2tf32(v3); al[mt][3] = f2tf32(v3 - __uint_as_float(ah[mt][3]));
            }
#pragma unroll
            for (int nt = 0; nt < 8; nt++) {
                const float* bb = Bs + (c0 + 8 * nt + g) * TS + kk + t;
                float w0 = bb[0], w1 = bb[4];
                uint32_t bh0 = f2tf32(w0), bh1 = f2tf32(w1);
                uint32_t bl0 = f2tf32(w0 - __uint_as_float(bh0));
                uint32_t bl1 = f2tf32(w1 - __uint_as_float(bh1));
#pragma unroll
                for (int mt = 0; mt < 2; mt++) {
                    mma_tf32(acc[mt][nt], ah[mt][0], ah[mt][1], ah[mt][2], ah[mt][3], bh0, bh1);
                    mma_tf32(acc[mt][nt], ah[mt][0], ah[mt][1], ah[mt][2], ah[mt][3], bl0, bl1);
                    mma_tf32(acc[mt][nt], al[mt][0], al[mt][1], al[mt][2], al[mt][3], bh0, bh1);
                }
            }
        }
    }
#pragma unroll
    for (int mt = 0; mt < 2; mt++) {
        float* O0 = out + (size_t)(row0 + r0 + 16 * mt + g) * ND + c0;
        float* O1 = O0 + 8 * (size_t)ND;
#pragma unroll
        for (int nt = 0; nt < 8; nt++) {
            *(float2*)(O0 + 8 * nt + 2 * t) = make_float2(acc[mt][nt][0], acc[mt][nt][1]);
            *(float2*)(O1 + 8 * nt + 2 * t) = make_float2(acc[mt][nt][2], acc[mt][nt][3]);
        }
    }
}

// ---------------------------------------------------------------------------
// MaxPool(2): phi -> phiP (row-major), g -> gPt (transposed [b][d][m])
// ---------------------------------------------------------------------------
__global__ __launch_bounds__(256) void pool_kernel()
{
    int idx4 = blockIdx.x * 256 + threadIdx.x;
    int total4 = NB * NM * ND / 4;
    if (idx4 >= total4) return;
    int d4 = idx4 % (ND / 4);
    int r  = (idx4 / (ND / 4)) % NM;
    int b  = idx4 / ((ND / 4) * NM);
    int src = ((b * NN + 2 * r) * ND) / 4 + d4;
    const float4* p = (const float4*)g_phi;
    const float4* g = (const float4*)g_gg;
    float4 a = p[src], a2 = p[src + ND / 4];
    float4 c = g[src], c2 = g[src + ND / 4];
    ((float4*)g_phiP)[idx4] = make_float4(fmaxf(a.x, a2.x), fmaxf(a.y, a2.y),
                                          fmaxf(a.z, a2.z), fmaxf(a.w, a2.w));
    int d0 = d4 * 4;
    g_gPt[(b * ND + d0 + 0) * NM + r] = fmaxf(c.x, c2.x);
    g_gPt[(b * ND + d0 + 1) * NM + r] = fmaxf(c.y, c2.y);
    g_gPt[(b * ND + d0 + 2) * NM + r] = fmaxf(c.z, c2.z);
    g_gPt[(b * ND + d0 + 3) * NM + r] = fmaxf(c.w, c2.w);
}

// ---------------------------------------------------------------------------
// Fused flash attention, 64 q-rows per CTA (2 CTAs/SM).
// 8 warps (4x2), warp tile 16 x 64.
// smem: Qs 64x132 | Ps 64x132 | KG 128x68 | stats 7x64  = 104192 B
// ---------------------------------------------------------------------------
#define QSTR 132
#define A_OFF_PS (64 * QSTR)
#define A_OFF_KG (2 * 64 * QSTR)
#define A_OFF_ST (2 * 64 * QSTR + 128 * TS)
#define ATTN_SMEM_FLOATS (A_OFF_ST + 7 * 64)

__global__ __launch_bounds__(256, 2) void attn_kernel()
{
    extern __shared__ float sm[];
    float* Qs   = sm;
    float* Ps   = sm + A_OFF_PS;
    float* KG   = sm + A_OFF_KG;
    float* rowm = sm + A_OFF_ST;
    float* rowl = rowm + 64;
    float* scal = rowl + 64;
    float* cmax = scal + 64;     // [2][64]
    float* csum = cmax + 128;    // [2][64]

    int tid = threadIdx.x;
    int b = blockIdx.y, q0 = blockIdx.x * 64;
    const float* Qp = g_theta + (size_t)(b * NN + q0) * ND;
    const float* Kp = g_phiP + (size_t)b * NM * ND;
    const float* Gp = g_gPt  + (size_t)b * ND * NM;

    int lane = tid & 31, g = lane >> 2, t = lane & 3;
    int wid = tid >> 5, wr = wid >> 1, wc = wid & 1;
    int r0 = wr * 16, c0 = wc * 64;

    // Stage Q tile 64x128
#pragma unroll
    for (int q = 0; q < 8; q++) {
        int li = q * 256 + tid, r = li >> 5, c = (li & 31) * 4;
        *(float4*)&Qs[r * QSTR + c] = *(const float4*)(Qp + r * ND + c);
    }
    if (tid < 64) { rowm[tid] = -1e30f; rowl[tid] = 0.f; }

    float yacc[8][4];
#pragma unroll
    for (int nt = 0; nt < 8; nt++)
#pragma unroll
        for (int i = 0; i < 4; i++) yacc[nt][i] = 0.f;

#pragma unroll 1
    for (int ch = 0; ch < 16; ch++) {
        int m0 = ch * 128;
        float sacc[8][4];
#pragma unroll
        for (int nt = 0; nt < 8; nt++)
#pragma unroll
            for (int i = 0; i < 4; i++) sacc[nt][i] = 0.f;

        // ---- Phase A: S[64x128] = Q @ K^T (3xTF32) ----
#pragma unroll 1
        for (int kc = 0; kc < 2; kc++) {
            int k0 = kc * 64;
            __syncthreads();
#pragma unroll
            for (int q = 0; q < 8; q++) {
                int li = q * 256 + tid, r = li >> 4, c = (li & 15) * 4;
                *(float4*)&KG[r * TS + c] = *(const float4*)(Kp + (size_t)(m0 + r) * ND + k0 + c);
            }
            __syncthreads();
#pragma unroll 2
            for (int kst = 0; kst < 8; kst++) {
                int kk = kst * 8;
                const float* ab = Qs + (r0 + g) * QSTR + k0 + kk + t;
                float v0 = ab[0], v1 = ab[8 * QSTR], v2 = ab[4], v3 = ab[8 * QSTR + 4];
                uint32_t ah0 = f2tf32(v0), al0 = f2tf32(v0 - __uint_as_float(ah0));
                uint32_t ah1 = f2tf32(v1), al1 = f2tf32(v1 - __uint_as_float(ah1));
                uint32_t ah2 = f2tf32(v2), al2 = f2tf32(v2 - __uint_as_float(ah2));
                uint32_t ah3 = f2tf32(v3), al3 = f2tf32(v3 - __uint_as_float(ah3));
#pragma unroll
                for (int nt = 0; nt < 8; nt++) {
                    const float* kb = KG + (c0 + 8 * nt + g) * TS + kk + t;
                    float w0 = kb[0], w1 = kb[4];
                    uint32_t bh0 = f2tf32(w0), bh1 = f2tf32(w1);
                    uint32_t bl0 = f2tf32(w0 - __uint_as_float(bh0));
                    uint32_t bl1 = f2tf32(w1 - __uint_as_float(bh1));
                    mma_tf32(sacc[nt], ah0, ah1, ah2, ah3, bh0, bh1);
                    mma_tf32(sacc[nt], ah0, ah1, ah2, ah3, bl0, bl1);
                    mma_tf32(sacc[nt], al0, al1, al2, al3, bh0, bh1);
                }
            }
        }

        // ---- Phase B: online softmax ----
        {
            float mx0 = -1e30f, mx1 = -1e30f;
#pragma unroll
            for (int nt = 0; nt < 8; nt++) {
                mx0 = fmaxf(mx0, fmaxf(sacc[nt][0], sacc[nt][1]));
                mx1 = fmaxf(mx1, fmaxf(sacc[nt][2], sacc[nt][3]));
            }
            mx0 = fmaxf(mx0, __shfl_xor_sync(0xFFFFFFFF, mx0, 1));
            mx0 = fmaxf(mx0, __shfl_xor_sync(0xFFFFFFFF, mx0, 2));
            mx1 = fmaxf(mx1, __shfl_xor_sync(0xFFFFFFFF, mx1, 1));
            mx1 = fmaxf(mx1, __shfl_xor_sync(0xFFFFFFFF, mx1, 2));
            if (t == 0) {
                cmax[wc * 64 + r0 + g]     = mx0;
                cmax[wc * 64 + r0 + g + 8] = mx1;
            }
        }
        __syncthreads();
        if (tid < 64) {
            float nm = fmaxf(rowm[tid], fmaxf(cmax[tid], cmax[64 + tid]));
            scal[tid] = __expf(rowm[tid] - nm);
            rowm[tid] = nm;
        }
        __syncthreads();
        {
            int ra = r0 + g, rb = ra + 8;
            float nma = rowm[ra], nmb = rowm[rb];
            float sum0 = 0.f, sum1 = 0.f;
#pragma unroll
            for (int nt = 0; nt < 8; nt++) {
                float p0 = __expf(sacc[nt][0] - nma);
                float p1 = __expf(sacc[nt][1] - nma);
                float p2 = __expf(sacc[nt][2] - nmb);
                float p3 = __expf(sacc[nt][3] - nmb);
                sum0 += p0 + p1; sum1 += p2 + p3;
                int cc = c0 + 8 * nt + 2 * t;
                *(float2*)&Ps[ra * QSTR + cc] = make_float2(p0, p1);
                *(float2*)&Ps[rb * QSTR + cc] = make_float2(p2, p3);
            }
            sum0 += __shfl_xor_sync(0xFFFFFFFF, sum0, 1);
            sum0 += __shfl_xor_sync(0xFFFFFFFF, sum0, 2);
            sum1 += __shfl_xor_sync(0xFFFFFFFF, sum1, 1);
            sum1 += __shfl_xor_sync(0xFFFFFFFF, sum1, 2);
            if (t == 0) { csum[wc * 64 + ra] = sum0; csum[wc * 64 + rb] = sum1; }
            float sa = scal[ra], sb = scal[rb];
#pragma unroll
            for (int nt = 0; nt < 8; nt++) {
                yacc[nt][0] *= sa; yacc[nt][1] *= sa;
                yacc[nt][2] *= sb; yacc[nt][3] *= sb;
            }
        }
        __syncthreads();
        if (tid < 64)
            rowl[tid] = rowl[tid] * scal[tid] + csum[tid] + csum[64 + tid];

        // ---- Phase C: Y += P @ G (1xTF32) ----
#pragma unroll 1
        for (int hc = 0; hc < 2; hc++) {
            int mh = hc * 64;
            __syncthreads();
#pragma unroll
            for (int q = 0; q < 8; q++) {
                int li = q * 256 + tid, r = li >> 4, c = (li & 15) * 4;
                *(float4*)&KG[r * TS + c] = *(const float4*)(Gp + (size_t)r * NM + m0 + mh + c);
            }
            __syncthreads();
#pragma unroll 2
            for (int kst = 0; kst < 8; kst++) {
                int kk = kst * 8;
                const float* ab = Ps + (r0 + g) * QSTR + mh + kk + t;
                uint32_t a0 = f2tf32(ab[0]);
                uint32_t a1 = f2tf32(ab[8 * QSTR]);
                uint32_t a2 = f2tf32(ab[4]);
                uint32_t a3 = f2tf32(ab[8 * QSTR + 4]);
#pragma unroll
                for (int nt = 0; nt < 8; nt++) {
                    const float* gb = KG + (c0 + 8 * nt + g) * TS + kk + t;
                    uint32_t b0 = f2tf32(gb[0]), b1 = f2tf32(gb[4]);
                    mma_tf32(yacc[nt], a0, a1, a2, a3, b0, b1);
                }
            }
        }
    }

    __syncthreads();
    {
        int ra = r0 + g, rb = ra + 8;
        float ia = 1.f / rowl[ra], ib = 1.f / rowl[rb];
        float* Y0 = g_y + (size_t)(b * NN + q0 + ra) * ND + c0;
        float* Y1 = g_y + (size_t)(b * NN + q0 + rb) * ND + c0;
#pragma unroll
        for (int nt = 0; nt < 8; nt++) {
            *(float2*)(Y0 + 8 * nt + 2 * t) = make_float2(yacc[nt][0] * ia, yacc[nt][1] * ia);
            *(float2*)(Y1 + 8 * nt + 2 * t) = make_float2(yacc[nt][2] * ib, yacc[nt][3] * ib);
        }
    }
}

// ---------------------------------------------------------------------------
// Output GEMM + residual (HMMA 3xTF32): out[32768,256] = x + y @ Wout
// Block 128 rows x 128 cols; grid (256, 2); K=128 in 2 chunks of 64.
// ---------------------------------------------------------------------------
__global__ __launch_bounds__(256, 2) void out_kernel(
    const float* __restrict__ x, const float* __restrict__ Wout, float* __restrict__ out)
{
    extern __shared__ float sm[];
    float* As = sm;              // 128 x TS (y rows)
    float* Bs = sm + 128 * TS;   // 128 x TS (Wout^T: n-major)

    int tid = threadIdx.x, row0 = blockIdx.x * 128, col0 = blockIdx.y * 128;
    int lane = tid & 31, g = lane >> 2, t = lane & 3;
    int wid = tid >> 5, wr = wid >> 1, wc = wid & 1;
    int r0 = wr * 32, c0 = wc * 64;

    float acc[2][8][4];
#pragma unroll
    for (int mt = 0; mt < 2; mt++)
#pragma unroll
        for (int nt = 0; nt < 8; nt++)
#pragma unroll
            for (int i = 0; i < 4; i++) acc[mt][nt][i] = 0.f;

#pragma unroll 1
    for (int kc = 0; kc < 2; kc++) {
        int k0 = kc * 64;
        __syncthreads();
#pragma unroll
        for (int q = 0; q < 8; q++) {
            int li = q * 256 + tid, r = li >> 4, c = (li & 15) * 4;
            *(float4*)&As[r * TS + c] = *(const float4*)(g_y + (size_t)(row0 + r) * ND + k0 + c);
        }
#pragma unroll
        for (int q = 0; q < 8; q++) {
            int li = q * 256 + tid, n = li & 127, kq = li >> 7;
            float4 v;
            v.x = Wout[(size_t)(k0 + kq * 4 + 0) * NC + col0 + n];
            v.y = Wout[(size_t)(k0 + kq * 4 + 1) * NC + col0 + n];
            v.z = Wout[(size_t)(k0 + kq * 4 + 2) * NC + col0 + n];
            v.w = Wout[(size_t)(k0 + kq * 4 + 3) * NC + col0 + n];
            *(float4*)&Bs[n * TS + kq * 4] = v;
        }
        __syncthreads();
#pragma unroll 2
        for (int kst = 0; kst < 8; kst++) {
            int kk = kst * 8;
            uint32_t ah[2][4], al[2][4];
#pragma unroll
            for (int mt = 0; mt < 2; mt++) {
                const float* ab = As + (r0 + 16 * mt + g) * TS + kk + t;
                float v0 = ab[0], v1 = ab[8 * TS], v2 = ab[4], v3 = ab[8 * TS + 4];
                ah[mt][0] = f2tf32(v0); al[mt][0] = f2tf32(v0 - __uint_as_float(ah[mt][0]));
                ah[mt][1] = f2tf32(v1); al[mt][1] = f2tf32(v1 - __uint_as_float(ah[mt][1]));
                ah[mt][2] = f2tf32(v2); al[mt][2] = f2tf32(v2 - __uint_as_float(ah[mt][2]));
                ah[mt][3] = f2tf32(v3); al[mt][3] = f2tf32(v3 - __uint_as_float(ah[mt][3]));
            }
#pragma unroll
            for (int nt = 0; nt < 8; nt++) {
                const float* bb = Bs + (c0 + 8 * nt + g) * TS + kk + t;
                float w0 = bb[0], w1 = bb[4];
                uint32_t bh0 = f2tf32(w0), bh1 = f2tf32(w1);
                uint32_t bl0 = f2tf32(w0 - __uint_as_float(bh0));
                uint32_t bl1 = f2tf32(w1 - __uint_as_float(bh1));
#pragma unroll
                for (int mt = 0; mt < 2; mt++) {
                    mma_tf32(acc[mt][nt], ah[mt][0], ah[mt][1], ah[mt][2], ah[mt][3], bh0, bh1);
                    mma_tf32(acc[mt][nt], ah[mt][0], ah[mt][1], ah[mt][2], ah[mt][3], bl0, bl1);
                    mma_tf32(acc[mt][nt], al[mt][0], al[mt][1], al[mt][2], al[mt][3], bh0, bh1);
                }
            }
        }
    }
#pragma unroll
    for (int mt = 0; mt < 2; mt++) {
        int ra = row0 + r0 + 16 * mt + g;
        const float* X0 = x + (size_t)ra * NC + col0 + c0;
        const float* X1 = X0 + 8 * (size_t)NC;
        float* O0 = out + (size_t)ra * NC + col0 + c0;
        float* O1 = O0 + 8 * (size_t)NC;
#pragma unroll
        for (int nt = 0; nt < 8; nt++) {
            int cc = 8 * nt + 2 * t;
            float2 x0 = *(const float2*)(X0 + cc);
            float2 x1 = *(const float2*)(X1 + cc);
            *(float2*)(O0 + cc) = make_float2(acc[mt][nt][0] + x0.x, acc[mt][nt][1] + x0.y);
            *(float2*)(O1 + cc) = make_float2(acc[mt][nt][2] + x1.x, acc[mt][nt][3] + x1.y);
        }
    }
}

// ---------------------------------------------------------------------------
extern "C" void kernel_launch(void* const* d_in, const int* in_sizes, int n_in,
                              void* d_out, int out_size)
{
    const float* x  = (const float*)d_in[0];
    const float* Wt = (const float*)d_in[1];
    const float* Wp = (const float*)d_in[2];
    const float* Wg = (const float*)d_in[3];
    const float* Wo = (const float*)d_in[4];
    float* out      = (float*)d_out;

    const int GEMM_SMEM = 2 * 128 * TS * 4;        // 69632 B
    const int ATTN_SMEM = ATTN_SMEM_FLOATS * 4;    // 104192 B
    cudaFuncSetAttribute(proj_kernel, cudaFuncAttributeMaxDynamicSharedMemorySize, GEMM_SMEM);
    cudaFuncSetAttribute(attn_kernel, cudaFuncAttributeMaxDynamicSharedMemorySize, ATTN_SMEM);
    cudaFuncSetAttribute(out_kernel,  cudaFuncAttributeMaxDynamicSharedMemorySize, GEMM_SMEM);

    proj_kernel<<<dim3(256, 1, 3), 256, GEMM_SMEM>>>(x, Wt, Wp, Wg);
    pool_kernel<<<(NB * NM * ND / 4 + 255) / 256, 256>>>();
    attn_kernel<<<dim3(64, 8), 256, ATTN_SMEM>>>();
    out_kernel<<<dim3(256, 2), 256, GEMM_SMEM>>>(x, Wo, out);
}

// round 8
// speedup vs baseline: 1.0004x; 1.0004x over previous
#include <cuda_runtime.h>
#include <cstdint>

// NonLocalBlock B=8, N=4096, M=2048, C=256, d=128
#define NB 8
#define NN 4096
#define NM 2048
#define NC 256
#define ND 128

__device__ float g_theta[NB * NN * ND];
__device__ float g_phi  [NB * NN * ND];
__device__ float g_gg   [NB * NN * ND];
__device__ float g_phiP [NB * NM * ND];          // [b][m][d]
__device__ float g_gPt  [NB * ND * NM];          // [b][d][m]
__device__ float g_y    [NB * NN * ND];

// ---------------------------------------------------------------------------
__device__ __forceinline__ uint32_t f2tf32(float v) {
    uint32_t r;
    asm("cvt.rna.tf32.f32 %0, %1;" : "=r"(r) : "f"(v));
    return r;
}
__device__ __forceinline__ void mma_tf32(float (&d)[4],
                                         uint32_t a0, uint32_t a1, uint32_t a2, uint32_t a3,
                                         uint32_t b0, uint32_t b1) {
    asm volatile(
        "mma.sync.aligned.m16n8k8.row.col.f32.tf32.tf32.f32 "
        "{%0,%1,%2,%3}, {%4,%5,%6,%7}, {%8,%9}, {%0,%1,%2,%3};"
        : "+f"(d[0]), "+f"(d[1]), "+f"(d[2]), "+f"(d[3])
        : "r"(a0), "r"(a1), "r"(a2), "r"(a3), "r"(b0), "r"(b1));
}

#define TS 68   // k-chunk tile stride (floats) for plain fp32 tiles

// ---------------------------------------------------------------------------
// Projection GEMM (HMMA 3xTF32): C[32768,128] = x[32768,256] @ W[256,128], x3
// (unchanged from R6)
// ---------------------------------------------------------------------------
__global__ __launch_bounds__(256, 2) void proj_kernel(
    const float* __restrict__ x, const float* __restrict__ Wt,
    const float* __restrict__ Wp, const float* __restrict__ Wg)
{
    extern __shared__ float sm[];
    float* As = sm;
    float* Bs = sm + 128 * TS;

    const float* W; float* out;
    if (blockIdx.z == 0)      { W = Wt; out = g_theta; }
    else if (blockIdx.z == 1) { W = Wp; out = g_phi; }
    else                      { W = Wg; out = g_gg; }

    int tid = threadIdx.x, row0 = blockIdx.x * 128;
    int lane = tid & 31, g = lane >> 2, t = lane & 3;
    int wid = tid >> 5, wr = wid >> 1, wc = wid & 1;
    int r0 = wr * 32, c0 = wc * 64;

    float acc[2][8][4];
#pragma unroll
    for (int mt = 0; mt < 2; mt++)
#pragma unroll
        for (int nt = 0; nt < 8; nt++)
#pragma unroll
            for (int i = 0; i < 4; i++) acc[mt][nt][i] = 0.f;

#pragma unroll 1
    for (int kc = 0; kc < 4; kc++) {
        int k0 = kc * 64;
        __syncthreads();
#pragma unroll
        for (int q = 0; q < 8; q++) {
            int li = q * 256 + tid, r = li >> 4, c = (li & 15) * 4;
            *(float4*)&As[r * TS + c] = *(const float4*)(x + (size_t)(row0 + r) * NC + k0 + c);
        }
#pragma unroll
        for (int q = 0; q < 8; q++) {
            int li = q * 256 + tid, n = li & 127, kq = li >> 7;
            float4 v;
            v.x = W[(size_t)(k0 + kq * 4 + 0) * ND + n];
            v.y = W[(size_t)(k0 + kq * 4 + 1) * ND + n];
            v.z = W[(size_t)(k0 + kq * 4 + 2) * ND + n];
            v.w = W[(size_t)(k0 + kq * 4 + 3) * ND + n];
            *(float4*)&Bs[n * TS + kq * 4] = v;
        }
        __syncthreads();
#pragma unroll 2
        for (int kst = 0; kst < 8; kst++) {
            int kk = kst * 8;
            uint32_t ah[2][4], al[2][4];
#pragma unroll
            for (int mt = 0; mt < 2; mt++) {
                const float* ab = As + (r0 + 16 * mt + g) * TS + kk + t;
                float v0 = ab[0], v1 = ab[8 * TS], v2 = ab[4], v3 = ab[8 * TS + 4];
                ah[mt][0] = f2tf32(v0); al[mt][0] = f2tf32(v0 - __uint_as_float(ah[mt][0]));
                ah[mt][1] = f2tf32(v1); al[mt][1] = f2tf32(v1 - __uint_as_float(ah[mt][1]));
                ah[mt][2] = f2tf32(v2); al[mt][2] = f2tf32(v2 - __uint_as_float(ah[mt][2]));
                ah[mt][3] = f2tf32(v3); al[mt][3] = f2tf32(v3 - __uint_as_float(ah[mt][3]));
            }
#pragma unroll
            for (int nt = 0; nt < 8; nt++) {
                const float* bb = Bs + (c0 + 8 * nt + g) * TS + kk + t;
                float w0 = bb[0], w1 = bb[4];
                uint32_t bh0 = f2tf32(w0), bh1 = f2tf32(w1);
                uint32_t bl0 = f2tf32(w0 - __uint_as_float(bh0));
                uint32_t bl1 = f2tf32(w1 - __uint_as_float(bh1));
#pragma unroll
                for (int mt = 0; mt < 2; mt++) {
                    mma_tf32(acc[mt][nt], ah[mt][0], ah[mt][1], ah[mt][2], ah[mt][3], bh0, bh1);
                    mma_tf32(acc[mt][nt], ah[mt][0], ah[mt][1], ah[mt][2], ah[mt][3], bl0, bl1);
                    mma_tf32(acc[mt][nt], al[mt][0], al[mt][1], al[mt][2], al[mt][3], bh0, bh1);
                }
            }
        }
    }
#pragma unroll
    for (int mt = 0; mt < 2; mt++) {
        float* O0 = out + (size_t)(row0 + r0 + 16 * mt + g) * ND + c0;
        float* O1 = O0 + 8 * (size_t)ND;
#pragma unroll
        for (int nt = 0; nt < 8; nt++) {
            *(float2*)(O0 + 8 * nt + 2 * t) = make_float2(acc[mt][nt][0], acc[mt][nt][1]);
            *(float2*)(O1 + 8 * nt + 2 * t) = make_float2(acc[mt][nt][2], acc[mt][nt][3]);
        }
    }
}

// ---------------------------------------------------------------------------
// MaxPool(2): phi -> phiP (row-major), g -> gPt (transposed [b][d][m])
// ---------------------------------------------------------------------------
__global__ __launch_bounds__(256) void pool_kernel()
{
    int idx4 = blockIdx.x * 256 + threadIdx.x;
    int total4 = NB * NM * ND / 4;
    if (idx4 >= total4) return;
    int d4 = idx4 % (ND / 4);
    int r  = (idx4 / (ND / 4)) % NM;
    int b  = idx4 / ((ND / 4) * NM);
    int src = ((b * NN + 2 * r) * ND) / 4 + d4;
    const float4* p = (const float4*)g_phi;
    const float4* g = (const float4*)g_gg;
    float4 a = p[src], a2 = p[src + ND / 4];
    float4 c = g[src], c2 = g[src + ND / 4];
    ((float4*)g_phiP)[idx4] = make_float4(fmaxf(a.x, a2.x), fmaxf(a.y, a2.y),
                                          fmaxf(a.z, a2.z), fmaxf(a.w, a2.w));
    int d0 = d4 * 4;
    g_gPt[(b * ND + d0 + 0) * NM + r] = fmaxf(c.x, c2.x);
    g_gPt[(b * ND + d0 + 1) * NM + r] = fmaxf(c.y, c2.y);
    g_gPt[(b * ND + d0 + 2) * NM + r] = fmaxf(c.z, c2.z);
    g_gPt[(b * ND + d0 + 3) * NM + r] = fmaxf(c.w, c2.w);
}

// ---------------------------------------------------------------------------
// Fused flash attention, 128 q-rows per CTA, 512 threads (16 warps, 4x4).
// Warp tile 32 rows x 32 cols.
// K staged as interleaved (hi,lo) tf32 float2; G and P stored as tf32 floats.
// smem (floats): Qs 128x132 | Ps 128x132 | KG2 128x66 float2 | stats 11x128
// ---------------------------------------------------------------------------
#define QSTR 132
#define KSTR2 66                                  // float2 units per KG row
#define A_OFF_PS (128 * QSTR)
#define A_OFF_KG (2 * 128 * QSTR)                 // float2 region, 128*66*2 floats
#define A_OFF_ST (2 * 128 * QSTR + 128 * KSTR2 * 2)
#define ATTN_SMEM_FLOATS (A_OFF_ST + 11 * 128)

__global__ __launch_bounds__(512, 1) void attn_kernel()
{
    extern __shared__ float sm[];
    float*  Qs   = sm;
    float*  Ps   = sm + A_OFF_PS;
    float2* KG2  = (float2*)(sm + A_OFF_KG);
    float*  rowm = sm + A_OFF_ST;
    float*  rowl = rowm + 128;
    float*  scal = rowl + 128;
    float*  cmax = scal + 128;     // [4][128]
    float*  csum = cmax + 512;     // [4][128]

    int tid = threadIdx.x;
    int b = blockIdx.y, q0 = blockIdx.x * 128;
    const float* Qp = g_theta + (size_t)(b * NN + q0) * ND;
    const float* Kp = g_phiP + (size_t)b * NM * ND;
    const float* Gp = g_gPt  + (size_t)b * ND * NM;

    int lane = tid & 31, g = lane >> 2, t = lane & 3;
    int wid = tid >> 5, wr = wid >> 2, wc = wid & 3;
    int r0 = wr * 32, c0 = wc * 32;

    // Stage Q tile 128x128 fp32
#pragma unroll
    for (int q = 0; q < 8; q++) {
        int li = q * 512 + tid, r = li >> 5, c = (li & 31) * 4;
        *(float4*)&Qs[r * QSTR + c] = *(const float4*)(Qp + r * ND + c);
    }
    if (tid < 128) { rowm[tid] = -1e30f; rowl[tid] = 0.f; }

    float yacc[2][4][4];
#pragma unroll
    for (int mt = 0; mt < 2; mt++)
#pragma unroll
        for (int nt = 0; nt < 4; nt++)
#pragma unroll
            for (int i = 0; i < 4; i++) yacc[mt][nt][i] = 0.f;

#pragma unroll 1
    for (int ch = 0; ch < 16; ch++) {
        int m0 = ch * 128;
        float sacc[2][4][4];
#pragma unroll
        for (int mt = 0; mt < 2; mt++)
#pragma unroll
            for (int nt = 0; nt < 4; nt++)
#pragma unroll
                for (int i = 0; i < 4; i++) sacc[mt][nt][i] = 0.f;

        // ---- Phase A: S[128x128] = Q @ K^T (3xTF32), K pre-split hi/lo ----
#pragma unroll 1
        for (int kc = 0; kc < 2; kc++) {
            int k0 = kc * 64;
            __syncthreads();   // KG reuse guard
            // Stage K chunk 128x64, split to (hi,lo) float2; 16 elems/thread
#pragma unroll
            for (int q = 0; q < 4; q++) {
                int li = q * 512 + tid, r = li >> 4, c = (li & 15) * 4;
                float4 v = *(const float4*)(Kp + (size_t)(m0 + r) * ND + k0 + c);
                uint32_t h0 = f2tf32(v.x), h1 = f2tf32(v.y), h2 = f2tf32(v.z), h3 = f2tf32(v.w);
                float2* dst = KG2 + r * KSTR2 + c;
                float4 p0, p1;
                p0.x = __uint_as_float(h0); p0.y = __uint_as_float(f2tf32(v.x - __uint_as_float(h0)));
                p0.z = __uint_as_float(h1); p0.w = __uint_as_float(f2tf32(v.y - __uint_as_float(h1)));
                p1.x = __uint_as_float(h2); p1.y = __uint_as_float(f2tf32(v.z - __uint_as_float(h2)));
                p1.z = __uint_as_float(h3); p1.w = __uint_as_float(f2tf32(v.w - __uint_as_float(h3)));
                *(float4*)(dst)     = p0;
                *(float4*)(dst + 2) = p1;
            }
            __syncthreads();
#pragma unroll 2
            for (int kst = 0; kst < 8; kst++) {
                int kk = kst * 8;
                uint32_t ah[2][4], al[2][4];
#pragma unroll
                for (int mt = 0; mt < 2; mt++) {
                    const float* ab = Qs + (r0 + 16 * mt + g) * QSTR + k0 + kk + t;
                    float v0 = ab[0], v1 = ab[8 * QSTR], v2 = ab[4], v3 = ab[8 * QSTR + 4];
                    ah[mt][0] = f2tf32(v0); al[mt][0] = f2tf32(v0 - __uint_as_float(ah[mt][0]));
                    ah[mt][1] = f2tf32(v1); al[mt][1] = f2tf32(v1 - __uint_as_float(ah[mt][1]));
                    ah[mt][2] = f2tf32(v2); al[mt][2] = f2tf32(v2 - __uint_as_float(ah[mt][2]));
                    ah[mt][3] = f2tf32(v3); al[mt][3] = f2tf32(v3 - __uint_as_float(ah[mt][3]));
                }
#pragma unroll
                for (int nt = 0; nt < 4; nt++) {
                    const float2* kb = KG2 + (c0 + 8 * nt + g) * KSTR2 + kk + t;
                    float2 hv0 = kb[0];   // (hi, lo) at k = kk+t
                    float2 hv1 = kb[4];   // (hi, lo) at k = kk+t+4
                    uint32_t bh0 = __float_as_uint(hv0.x), bl0 = __float_as_uint(hv0.y);
                    uint32_t bh1 = __float_as_uint(hv1.x), bl1 = __float_as_uint(hv1.y);
#pragma unroll
                    for (int mt = 0; mt < 2; mt++) {
                        mma_tf32(sacc[mt][nt], ah[mt][0], ah[mt][1], ah[mt][2], ah[mt][3], bh0, bh1);
                        mma_tf32(sacc[mt][nt], ah[mt][0], ah[mt][1], ah[mt][2], ah[mt][3], bl0, bl1);
                        mma_tf32(sacc[mt][nt], al[mt][0], al[mt][1], al[mt][2], al[mt][3], bh0, bh1);
                    }
                }
            }
        }

        // ---- Phase B: online softmax ----
#pragma unroll
        for (int mt = 0; mt < 2; mt++) {
            float mx0 = -1e30f, mx1 = -1e30f;
#pragma unroll
            for (int nt = 0; nt < 4; nt++) {
                mx0 = fmaxf(mx0, fmaxf(sacc[mt][nt][0], sacc[mt][nt][1]));
                mx1 = fmaxf(mx1, fmaxf(sacc[mt][nt][2], sacc[mt][nt][3]));
            }
            mx0 = fmaxf(mx0, __shfl_xor_sync(0xFFFFFFFF, mx0, 1));
            mx0 = fmaxf(mx0, __shfl_xor_sync(0xFFFFFFFF, mx0, 2));
            mx1 = fmaxf(mx1, __shfl_xor_sync(0xFFFFFFFF, mx1, 1));
            mx1 = fmaxf(mx1, __shfl_xor_sync(0xFFFFFFFF, mx1, 2));
            if (t == 0) {
                cmax[wc * 128 + r0 + 16 * mt + g]     = mx0;
                cmax[wc * 128 + r0 + 16 * mt + g + 8] = mx1;
            }
        }
        __syncthreads();
        if (tid < 128) {
            float nm = fmaxf(fmaxf(rowm[tid], fmaxf(cmax[tid], cmax[128 + tid])),
                             fmaxf(cmax[256 + tid], cmax[384 + tid]));
            scal[tid] = __expf(rowm[tid] - nm);
            rowm[tid] = nm;
        }
        __syncthreads();
#pragma unroll
        for (int mt = 0; mt < 2; mt++) {
            int ra = r0 + 16 * mt + g, rb = ra + 8;
            float nma = rowm[ra], nmb = rowm[rb];
            float sum0 = 0.f, sum1 = 0.f;
#pragma unroll
            for (int nt = 0; nt < 4; nt++) {
                // round P to tf32 at write; sums use the rounded values
                float p0 = __uint_as_float(f2tf32(__expf(sacc[mt][nt][0] - nma)));
                float p1 = __uint_as_float(f2tf32(__expf(sacc[mt][nt][1] - nma)));
                float p2 = __uint_as_float(f2tf32(__expf(sacc[mt][nt][2] - nmb)));
                float p3 = __uint_as_float(f2tf32(__expf(sacc[mt][nt][3] - nmb)));
                sum0 += p0 + p1; sum1 += p2 + p3;
                int cc = c0 + 8 * nt + 2 * t;
                *(float2*)&Ps[ra * QSTR + cc] = make_float2(p0, p1);
                *(float2*)&Ps[rb * QSTR + cc] = make_float2(p2, p3);
            }
            sum0 += __shfl_xor_sync(0xFFFFFFFF, sum0, 1);
            sum0 += __shfl_xor_sync(0xFFFFFFFF, sum0, 2);
            sum1 += __shfl_xor_sync(0xFFFFFFFF, sum1, 1);
            sum1 += __shfl_xor_sync(0xFFFFFFFF, sum1, 2);
            if (t == 0) {
                csum[wc * 128 + ra] = sum0;
                csum[wc * 128 + rb] = sum1;
            }
            float sa = scal[ra], sb = scal[rb];
#pragma unroll
            for (int nt = 0; nt < 4; nt++) {
                yacc[mt][nt][0] *= sa; yacc[mt][nt][1] *= sa;
                yacc[mt][nt][2] *= sb; yacc[mt][nt][3] *= sb;
            }
        }
        __syncthreads();
        if (tid < 128)
            rowl[tid] = rowl[tid] * scal[tid]
                      + csum[tid] + csum[128 + tid] + csum[256 + tid] + csum[384 + tid];

        // ---- Phase C: Y += P @ G (1xTF32), G stored as tf32 floats ----
#pragma unroll 1
        for (int hc = 0; hc < 2; hc++) {
            int mh = hc * 64;
            __syncthreads();
            // Stage G chunk 128(d) x 64(m) as tf32 floats in KG2[].x
#pragma unroll
            for (int q = 0; q < 4; q++) {
                int li = q * 512 + tid, r = li >> 4, c = (li & 15) * 4;
                float4 v = *(const float4*)(Gp + (size_t)r * NM + m0 + mh + c);
                float2* dst = KG2 + r * KSTR2 + c;
                dst[0].x = __uint_as_float(f2tf32(v.x));
                dst[1].x = __uint_as_float(f2tf32(v.y));
                dst[2].x = __uint_as_float(f2tf32(v.z));
                dst[3].x = __uint_as_float(f2tf32(v.w));
            }
            __syncthreads();
#pragma unroll 2
            for (int kst = 0; kst < 8; kst++) {
                int kk = kst * 8;
                uint32_t a[2][4];
#pragma unroll
                for (int mt = 0; mt < 2; mt++) {
                    const float* ab = Ps + (r0 + 16 * mt + g) * QSTR + mh + kk + t;
                    a[mt][0] = __float_as_uint(ab[0]);
                    a[mt][1] = __float_as_uint(ab[8 * QSTR]);
                    a[mt][2] = __float_as_uint(ab[4]);
                    a[mt][3] = __float_as_uint(ab[8 * QSTR + 4]);
                }
#pragma unroll
                for (int nt = 0; nt < 4; nt++) {
                    const float2* gb = KG2 + (c0 + 8 * nt + g) * KSTR2 + kk + t;
                    uint32_t b0 = __float_as_uint(gb[0].x);
                    uint32_t b1 = __float_as_uint(gb[4].x);
#pragma unroll
                    for (int mt = 0; mt < 2; mt++)
                        mma_tf32(yacc[mt][nt], a[mt][0], a[mt][1], a[mt][2], a[mt][3], b0, b1);
                }
            }
        }
    }

    __syncthreads();
#pragma unroll
    for (int mt = 0; mt < 2; mt++) {
        int ra = r0 + 16 * mt + g, rb = ra + 8;
        float ia = 1.f / rowl[ra], ib = 1.f / rowl[rb];
        float* Y0 = g_y + (size_t)(b * NN + q0 + ra) * ND + c0;
        float* Y1 = g_y + (size_t)(b * NN + q0 + rb) * ND + c0;
#pragma unroll
        for (int nt = 0; nt < 4; nt++) {
            *(float2*)(Y0 + 8 * nt + 2 * t) = make_float2(yacc[mt][nt][0] * ia, yacc[mt][nt][1] * ia);
            *(float2*)(Y1 + 8 * nt + 2 * t) = make_float2(yacc[mt][nt][2] * ib, yacc[mt][nt][3] * ib);
        }
    }
}

// ---------------------------------------------------------------------------
// Output GEMM + residual (HMMA 3xTF32) — unchanged from R6 (measured 57us)
// ---------------------------------------------------------------------------
__global__ __launch_bounds__(256, 2) void out_kernel(
    const float* __restrict__ x, const float* __restrict__ Wout, float* __restrict__ out)
{
    extern __shared__ float sm[];
    float* As = sm;
    float* Bs = sm + 128 * TS;

    int tid = threadIdx.x, row0 = blockIdx.x * 128, col0 = blockIdx.y * 128;
    int lane = tid & 31, g = lane >> 2, t = lane & 3;
    int wid = tid >> 5, wr = wid >> 1, wc = wid & 1;
    int r0 = wr * 32, c0 = wc * 64;

    float acc[2][8][4];
#pragma unroll
    for (int mt = 0; mt < 2; mt++)
#pragma unroll
        for (int nt = 0; nt < 8; nt++)
#pragma unroll
            for (int i = 0; i < 4; i++) acc[mt][nt][i] = 0.f;

#pragma unroll 1
    for (int kc = 0; kc < 2; kc++) {
        int k0 = kc * 64;
        __syncthreads();
#pragma unroll
        for (int q = 0; q < 8; q++) {
            int li = q * 256 + tid, r = li >> 4, c = (li & 15) * 4;
            *(float4*)&As[r * TS + c] = *(const float4*)(g_y + (size_t)(row0 + r) * ND + k0 + c);
        }
#pragma unroll
        for (int q = 0; q < 8; q++) {
            int li = q * 256 + tid, n = li & 127, kq = li >> 7;
            float4 v;
            v.x = Wout[(size_t)(k0 + kq * 4 + 0) * NC + col0 + n];
            v.y = Wout[(size_t)(k0 + kq * 4 + 1) * NC + col0 + n];
            v.z = Wout[(size_t)(k0 + kq * 4 + 2) * NC + col0 + n];
            v.w = Wout[(size_t)(k0 + kq * 4 + 3) * NC + col0 + n];
            *(float4*)&Bs[n * TS + kq * 4] = v;
        }
        __syncthreads();
#pragma unroll 2
        for (int kst = 0; kst < 8; kst++) {
            int kk = kst * 8;
            uint32_t ah[2][4], al[2][4];
#pragma unroll
            for (int mt = 0; mt < 2; mt++) {
                const float* ab = As + (r0 + 16 * mt + g) * TS + kk + t;
                float v0 = ab[0], v1 = ab[8 * TS], v2 = ab[4], v3 = ab[8 * TS + 4];
                ah[mt][0] = f2tf32(v0); al[mt][0] = f2tf32(v0 - __uint_as_float(ah[mt][0]));
                ah[mt][1] = f2tf32(v1); al[mt][1] = f2tf32(v1 - __uint_as_float(ah[mt][1]));
                ah[mt][2] = f2tf32(v2); al[mt][2] = f2tf32(v2 - __uint_as_float(ah[mt][2]));
                ah[mt][3] = f2tf32(v3); al[mt][3] = f2tf32(v3 - __uint_as_float(ah[mt][3]));
            }
#pragma unroll
            for (int nt = 0; nt < 8; nt++) {
                const float* bb = Bs + (c0 + 8 * nt + g) * TS + kk + t;
                float w0 = bb[0], w1 = bb[4];
                uint32_t bh0 = f2tf32(w0), bh1 = f2tf32(w1);
                uint32_t bl0 = f2tf32(w0 - __uint_as_float(bh0));
                uint32_t bl1 = f2tf32(w1 - __uint_as_float(bh1));
#pragma unroll
                for (int mt = 0; mt < 2; mt++) {
                    mma_tf32(acc[mt][nt], ah[mt][0], ah[mt][1], ah[mt][2], ah[mt][3], bh0, bh1);
                    mma_tf32(acc[mt][nt], ah[mt][0], ah[mt][1], ah[mt][2], ah[mt][3], bl0, bl1);
                    mma_tf32(acc[mt][nt], al[mt][0], al[mt][1], al[mt][2], al[mt][3], bh0, bh1);
                }
            }
        }
    }
#pragma unroll
    for (int mt = 0; mt < 2; mt++) {
        int ra = row0 + r0 + 16 * mt + g;
        const float* X0 = x + (size_t)ra * NC + col0 + c0;
        const float* X1 = X0 + 8 * (size_t)NC;
        float* O0 = out + (size_t)ra * NC + col0 + c0;
        float* O1 = O0 + 8 * (size_t)NC;
#pragma unroll
        for (int nt = 0; nt < 8; nt++) {
            int cc = 8 * nt + 2 * t;
            float2 x0 = *(const float2*)(X0 + cc);
            float2 x1 = *(const float2*)(X1 + cc);
            *(float2*)(O0 + cc) = make_float2(acc[mt][nt][0] + x0.x, acc[mt][nt][1] + x0.y);
            *(float2*)(O1 + cc) = make_float2(acc[mt][nt][2] + x1.x, acc[mt][nt][3] + x1.y);
        }
    }
}

// ---------------------------------------------------------------------------
extern "C" void kernel_launch(void* const* d_in, const int* in_sizes, int n_in,
                              void* d_out, int out_size)
{
    const float* x  = (const float*)d_in[0];
    const float* Wt = (const float*)d_in[1];
    const float* Wp = (const float*)d_in[2];
    const float* Wg = (const float*)d_in[3];
    const float* Wo = (const float*)d_in[4];
    float* out      = (float*)d_out;

    const int GEMM_SMEM = 2 * 128 * TS * 4;        // 69632 B
    const int ATTN_SMEM = ATTN_SMEM_FLOATS * 4;    // 208384 B
    cudaFuncSetAttribute(proj_kernel, cudaFuncAttributeMaxDynamicSharedMemorySize, GEMM_SMEM);
    cudaFuncSetAttribute(attn_kernel, cudaFuncAttributeMaxDynamicSharedMemorySize, ATTN_SMEM);
    cudaFuncSetAttribute(out_kernel,  cudaFuncAttributeMaxDynamicSharedMemorySize, GEMM_SMEM);

    proj_kernel<<<dim3(256, 1, 3), 256, GEMM_SMEM>>>(x, Wt, Wp, Wg);
    pool_kernel<<<(NB * NM * ND / 4 + 255) / 256, 256>>>();
    attn_kernel<<<dim3(32, 8), 512, ATTN_SMEM>>>();
    out_kernel<<<dim3(256, 2), 256, GEMM_SMEM>>>(x, Wo, out);
}

// round 9
// speedup vs baseline: 1.1409x; 1.1404x over previous
#include <cuda_runtime.h>
#include <cstdint>

// NonLocalBlock B=8, N=4096, M=2048, C=256, d=128
#define NB 8
#define NN 4096
#define NM 2048
#define NC 256
#define ND 128

__device__ float g_theta[NB * NN * ND];
__device__ float g_phi  [NB * NN * ND];
__device__ float g_gg   [NB * NN * ND];
__device__ float g_phiP [NB * NM * ND];          // [b][m][d]
__device__ float g_gPt  [NB * ND * NM];          // [b][d][m]
__device__ float g_S    [NB * NN * NM];          // raw logits (256 MB)
__device__ float g_y    [NB * NN * ND];

// ---------------------------------------------------------------------------
__device__ __forceinline__ uint32_t f2tf32(float v) {
    uint32_t r;
    asm("cvt.rna.tf32.f32 %0, %1;" : "=r"(r) : "f"(v));
    return r;
}
__device__ __forceinline__ float tf32r(float v) { return __uint_as_float(f2tf32(v)); }
__device__ __forceinline__ void mma_tf32(float (&d)[4],
                                         uint32_t a0, uint32_t a1, uint32_t a2, uint32_t a3,
                                         uint32_t b0, uint32_t b1) {
    asm volatile(
        "mma.sync.aligned.m16n8k8.row.col.f32.tf32.tf32.f32 "
        "{%0,%1,%2,%3}, {%4,%5,%6,%7}, {%8,%9}, {%0,%1,%2,%3};"
        : "+f"(d[0]), "+f"(d[1]), "+f"(d[2]), "+f"(d[3])
        : "r"(a0), "r"(a1), "r"(a2), "r"(a3), "r"(b0), "r"(b1));
}

#define TS 68      // plain fp32 tile stride (floats)
#define PS2 66     // pre-split tile stride (float2 units; 132 floats/row)

// ===========================================================================
// Projection GEMM (HMMA 3xTF32, pre-split B): C = x @ W, x3 weights
// Block 128x128, K=256 in 4 chunks of 64. smem: As 128x68 f32 | Bs2 128x66 f2
// ===========================================================================
__global__ __launch_bounds__(256, 2) void proj_kernel(
    const float* __restrict__ x, const float* __restrict__ Wt,
    const float* __restrict__ Wp, const float* __restrict__ Wg)
{
    extern __shared__ float sm[];
    float*  As  = sm;
    float2* Bs2 = (float2*)(sm + 128 * TS);

    const float* W; float* out;
    if (blockIdx.z == 0)      { W = Wt; out = g_theta; }
    else if (blockIdx.z == 1) { W = Wp; out = g_phi; }
    else                      { W = Wg; out = g_gg; }

    int tid = threadIdx.x, row0 = blockIdx.x * 128;
    int lane = tid & 31, g = lane >> 2, t = lane & 3;
    int wid = tid >> 5, wr = wid >> 1, wc = wid & 1;
    int r0 = wr * 32, c0 = wc * 64;

    float acc[2][8][4];
#pragma unroll
    for (int mt = 0; mt < 2; mt++)
#pragma unroll
        for (int nt = 0; nt < 8; nt++)
#pragma unroll
            for (int i = 0; i < 4; i++) acc[mt][nt][i] = 0.f;

#pragma unroll 1
    for (int kc = 0; kc < 4; kc++) {
        int k0 = kc * 64;
        __syncthreads();
#pragma unroll
        for (int q = 0; q < 8; q++) {
            int li = q * 256 + tid, r = li >> 4, c = (li & 15) * 4;
            *(float4*)&As[r * TS + c] = *(const float4*)(x + (size_t)(row0 + r) * NC + k0 + c);
        }
#pragma unroll
        for (int q = 0; q < 8; q++) {
            int li = q * 256 + tid, n = li & 127, kq = li >> 7;
            float w0 = W[(size_t)(k0 + kq * 4 + 0) * ND + n];
            float w1 = W[(size_t)(k0 + kq * 4 + 1) * ND + n];
            float w2 = W[(size_t)(k0 + kq * 4 + 2) * ND + n];
            float w3 = W[(size_t)(k0 + kq * 4 + 3) * ND + n];
            float* dst = (float*)(Bs2 + n * PS2 + kq * 4);
            float h0 = tf32r(w0), h1 = tf32r(w1), h2 = tf32r(w2), h3 = tf32r(w3);
            *(float4*)(dst)     = make_float4(h0, tf32r(w0 - h0), h1, tf32r(w1 - h1));
            *(float4*)(dst + 4) = make_float4(h2, tf32r(w2 - h2), h3, tf32r(w3 - h3));
        }
        __syncthreads();
#pragma unroll 2
        for (int kst = 0; kst < 8; kst++) {
            int kk = kst * 8;
            uint32_t ah[2][4], al[2][4];
#pragma unroll
            for (int mt = 0; mt < 2; mt++) {
                const float* ab = As + (r0 + 16 * mt + g) * TS + kk + t;
                float v0 = ab[0], v1 = ab[8 * TS], v2 = ab[4], v3 = ab[8 * TS + 4];
                ah[mt][0] = f2tf32(v0); al[mt][0] = f2tf32(v0 - __uint_as_float(ah[mt][0]));
                ah[mt][1] = f2tf32(v1); al[mt][1] = f2tf32(v1 - __uint_as_float(ah[mt][1]));
                ah[mt][2] = f2tf32(v2); al[mt][2] = f2tf32(v2 - __uint_as_float(ah[mt][2]));
                ah[mt][3] = f2tf32(v3); al[mt][3] = f2tf32(v3 - __uint_as_float(ah[mt][3]));
            }
#pragma unroll
            for (int nt = 0; nt < 8; nt++) {
                const float2* bb = Bs2 + (c0 + 8 * nt + g) * PS2 + kk + t;
                float2 hv0 = bb[0], hv1 = bb[4];
                uint32_t bh0 = __float_as_uint(hv0.x), bl0 = __float_as_uint(hv0.y);
                uint32_t bh1 = __float_as_uint(hv1.x), bl1 = __float_as_uint(hv1.y);
#pragma unroll
                for (int mt = 0; mt < 2; mt++) {
                    mma_tf32(acc[mt][nt], ah[mt][0], ah[mt][1], ah[mt][2], ah[mt][3], bh0, bh1);
                    mma_tf32(acc[mt][nt], ah[mt][0], ah[mt][1], ah[mt][2], ah[mt][3], bl0, bl1);
                    mma_tf32(acc[mt][nt], al[mt][0], al[mt][1], al[mt][2], al[mt][3], bh0, bh1);
                }
            }
        }
    }
#pragma unroll
    for (int mt = 0; mt < 2; mt++) {
        float* O0 = out + (size_t)(row0 + r0 + 16 * mt + g) * ND + c0;
        float* O1 = O0 + 8 * (size_t)ND;
#pragma unroll
        for (int nt = 0; nt < 8; nt++) {
            *(float2*)(O0 + 8 * nt + 2 * t) = make_float2(acc[mt][nt][0], acc[mt][nt][1]);
            *(float2*)(O1 + 8 * nt + 2 * t) = make_float2(acc[mt][nt][2], acc[mt][nt][3]);
        }
    }
}

// ===========================================================================
// MaxPool(2): phi -> phiP (row-major), g -> gPt (transposed [b][d][m])
// ===========================================================================
__global__ __launch_bounds__(256) void pool_kernel()
{
    int idx4 = blockIdx.x * 256 + threadIdx.x;
    int total4 = NB * NM * ND / 4;
    if (idx4 >= total4) return;
    int d4 = idx4 % (ND / 4);
    int r  = (idx4 / (ND / 4)) % NM;
    int b  = idx4 / ((ND / 4) * NM);
    int src = ((b * NN + 2 * r) * ND) / 4 + d4;
    const float4* p = (const float4*)g_phi;
    const float4* g = (const float4*)g_gg;
    float4 a = p[src], a2 = p[src + ND / 4];
    float4 c = g[src], c2 = g[src + ND / 4];
    ((float4*)g_phiP)[idx4] = make_float4(fmaxf(a.x, a2.x), fmaxf(a.y, a2.y),
                                          fmaxf(a.z, a2.z), fmaxf(a.w, a2.w));
    int d0 = d4 * 4;
    g_gPt[(b * ND + d0 + 0) * NM + r] = fmaxf(c.x, c2.x);
    g_gPt[(b * ND + d0 + 1) * NM + r] = fmaxf(c.y, c2.y);
    g_gPt[(b * ND + d0 + 2) * NM + r] = fmaxf(c.z, c2.z);
    g_gPt[(b * ND + d0 + 3) * NM + r] = fmaxf(c.w, c2.w);
}

// ===========================================================================
// GEMM1 (HMMA 3xTF32, pre-split K): S_raw[128x128] = theta @ phiP^T, K=128
// grid (32 qtiles, 16 mtiles, 8 b). smem: Qs 128x68 f32 | Ks2 128x66 f2
// ===========================================================================
__global__ __launch_bounds__(256, 2) void qk_kernel()
{
    extern __shared__ float sm[];
    float*  Qs  = sm;
    float2* Ks2 = (float2*)(sm + 128 * TS);

    int tid = threadIdx.x;
    int b = blockIdx.z, q0 = blockIdx.x * 128, m0 = blockIdx.y * 128;
    const float* Ap = g_theta + (size_t)(b * NN + q0) * ND;
    const float* Bp = g_phiP + (size_t)(b * NM + m0) * ND;

    int lane = tid & 31, g = lane >> 2, t = lane & 3;
    int wid = tid >> 5, wr = wid >> 1, wc = wid & 1;
    int r0 = wr * 32, c0 = wc * 64;

    float acc[2][8][4];
#pragma unroll
    for (int mt = 0; mt < 2; mt++)
#pragma unroll
        for (int nt = 0; nt < 8; nt++)
#pragma unroll
            for (int i = 0; i < 4; i++) acc[mt][nt][i] = 0.f;

#pragma unroll 1
    for (int kc = 0; kc < 2; kc++) {
        int k0 = kc * 64;
        __syncthreads();
#pragma unroll
        for (int q = 0; q < 8; q++) {
            int li = q * 256 + tid, r = li >> 4, c = (li & 15) * 4;
            *(float4*)&Qs[r * TS + c] = *(const float4*)(Ap + (size_t)r * ND + k0 + c);
            float4 v = *(const float4*)(Bp + (size_t)r * ND + k0 + c);
            float h0 = tf32r(v.x), h1 = tf32r(v.y), h2 = tf32r(v.z), h3 = tf32r(v.w);
            float* dst = (float*)(Ks2 + r * PS2 + c);
            *(float4*)(dst)     = make_float4(h0, tf32r(v.x - h0), h1, tf32r(v.y - h1));
            *(float4*)(dst + 4) = make_float4(h2, tf32r(v.z - h2), h3, tf32r(v.w - h3));
        }
        __syncthreads();
#pragma unroll 2
        for (int kst = 0; kst < 8; kst++) {
            int kk = kst * 8;
            uint32_t ah[2][4], al[2][4];
#pragma unroll
            for (int mt = 0; mt < 2; mt++) {
                const float* ab = Qs + (r0 + 16 * mt + g) * TS + kk + t;
                float v0 = ab[0], v1 = ab[8 * TS], v2 = ab[4], v3 = ab[8 * TS + 4];
                ah[mt][0] = f2tf32(v0); al[mt][0] = f2tf32(v0 - __uint_as_float(ah[mt][0]));
                ah[mt][1] = f2tf32(v1); al[mt][1] = f2tf32(v1 - __uint_as_float(ah[mt][1]));
                ah[mt][2] = f2tf32(v2); al[mt][2] = f2tf32(v2 - __uint_as_float(ah[mt][2]));
                ah[mt][3] = f2tf32(v3); al[mt][3] = f2tf32(v3 - __uint_as_float(ah[mt][3]));
            }
#pragma unroll
            for (int nt = 0; nt < 8; nt++) {
                const float2* kb = Ks2 + (c0 + 8 * nt + g) * PS2 + kk + t;
                float2 hv0 = kb[0], hv1 = kb[4];
                uint32_t bh0 = __float_as_uint(hv0.x), bl0 = __float_as_uint(hv0.y);
                uint32_t bh1 = __float_as_uint(hv1.x), bl1 = __float_as_uint(hv1.y);
#pragma unroll
                for (int mt = 0; mt < 2; mt++) {
                    mma_tf32(acc[mt][nt], ah[mt][0], ah[mt][1], ah[mt][2], ah[mt][3], bh0, bh1);
                    mma_tf32(acc[mt][nt], ah[mt][0], ah[mt][1], ah[mt][2], ah[mt][3], bl0, bl1);
                    mma_tf32(acc[mt][nt], al[mt][0], al[mt][1], al[mt][2], al[mt][3], bh0, bh1);
                }
            }
        }
    }
    // write RAW logits
#pragma unroll
    for (int mt = 0; mt < 2; mt++) {
        float* So0 = g_S + (size_t)(b * NN + q0 + r0 + 16 * mt + g) * NM + m0 + c0;
        float* So1 = So0 + 8 * (size_t)NM;
#pragma unroll
        for (int nt = 0; nt < 8; nt++) {
            *(float2*)(So0 + 8 * nt + 2 * t) = make_float2(acc[mt][nt][0], acc[mt][nt][1]);
            *(float2*)(So1 + 8 * nt + 2 * t) = make_float2(acc[mt][nt][2], acc[mt][nt][3]);
        }
    }
}

// ===========================================================================
// Fused softmax + PV (HMMA 1xTF32): Y[128x128] with online softmax over
// raw-logit chunks of 64 keys read from g_S.  grid (32 qtiles, 8 b).
// smem: Ss 128x68 (logits -> P tf32) | Gs 128x68 (G tf32) | stats
// ===========================================================================
#define PV_OFF_GS (128 * TS)
#define PV_OFF_ST (2 * 128 * TS)
#define PV_SMEM_FLOATS (PV_OFF_ST + 256 + 256 + 3 * 128)

__global__ __launch_bounds__(256, 2) void pv_kernel()
{
    extern __shared__ float sm[];
    float* Ss      = sm;
    float* Gs      = sm + PV_OFF_GS;
    float* pairmax = sm + PV_OFF_ST;        // [256]
    float* pairsum = pairmax + 256;         // [256]
    float* rowm    = pairsum + 256;         // [128]
    float* rowl    = rowm + 128;            // [128]
    float* scal    = rowl + 128;            // [128]

    int tid = threadIdx.x;
    int b = blockIdx.y, q0 = blockIdx.x * 128;
    const float* Sp = g_S + (size_t)(b * NN + q0) * NM;
    const float* Gp = g_gPt + (size_t)b * ND * NM;

    int lane = tid & 31, g = lane >> 2, t = lane & 3;
    int wid = tid >> 5, wr = wid >> 1, wc = wid & 1;
    int r0 = wr * 32, c0 = wc * 64;
    int srow = tid >> 1, shalf = (tid & 1) * 32;   // stats ownership

    if (tid < 128) { rowm[tid] = -1e30f; rowl[tid] = 0.f; }

    float yacc[2][8][4];
#pragma unroll
    for (int mt = 0; mt < 2; mt++)
#pragma unroll
        for (int nt = 0; nt < 8; nt++)
#pragma unroll
            for (int i = 0; i < 4; i++) yacc[mt][nt][i] = 0.f;

#pragma unroll 1
    for (int ch = 0; ch < 32; ch++) {
        int m0 = ch * 64;
        __syncthreads();   // guard Ss/Gs/stats from previous iteration readers
        // Stage raw S chunk [128q x 64m] and G chunk [128d x 64m] (tf32)
#pragma unroll
        for (int q = 0; q < 8; q++) {
            int li = q * 256 + tid, r = li >> 4, c = (li & 15) * 4;
            *(float4*)&Ss[r * TS + c] = *(const float4*)(Sp + (size_t)r * NM + m0 + c);
            float4 v = *(const float4*)(Gp + (size_t)r * NM + m0 + c);
            *(float4*)&Gs[r * TS + c] = make_float4(tf32r(v.x), tf32r(v.y), tf32r(v.z), tf32r(v.w));
        }
        __syncthreads();
        // chunk row max (2 threads per row, 32 values each)
        {
            const float* base = Ss + srow * TS + shalf;
            float mx = -1e30f;
#pragma unroll
            for (int j = 0; j < 8; j++) {
                float4 v = *(const float4*)(base + j * 4);
                mx = fmaxf(mx, fmaxf(fmaxf(v.x, v.y), fmaxf(v.z, v.w)));
            }
            pairmax[tid] = mx;
        }
        __syncthreads();
        if (tid < 128) {
            float nm = fmaxf(rowm[tid], fmaxf(pairmax[2 * tid], pairmax[2 * tid + 1]));
            scal[tid] = __expf(rowm[tid] - nm);
            rowm[tid] = nm;
        }
        __syncthreads();
        // exp pass: P = tf32(exp(S - nm)) written back; partial sums
        {
            float nm = rowm[srow];
            float* base = Ss + srow * TS + shalf;
            float sum = 0.f;
#pragma unroll
            for (int j = 0; j < 8; j++) {
                float4 v = *(float4*)(base + j * 4);
                v.x = tf32r(__expf(v.x - nm)); v.y = tf32r(__expf(v.y - nm));
                v.z = tf32r(__expf(v.z - nm)); v.w = tf32r(__expf(v.w - nm));
                sum += v.x + v.y + v.z + v.w;
                *(float4*)(base + j * 4) = v;
            }
            pairsum[tid] = sum;
        }
        __syncthreads();
        if (tid < 128)
            rowl[tid] = rowl[tid] * scal[tid] + pairsum[2 * tid] + pairsum[2 * tid + 1];
        // Y rescale + MMA over this chunk (K = 64)
        {
            int ra = r0 + g, rb = ra + 8, rc = ra + 16, rd = ra + 24;
            float s0 = scal[ra], s1 = scal[rb], s2 = scal[rc], s3 = scal[rd];
#pragma unroll
            for (int nt = 0; nt < 8; nt++) {
                yacc[0][nt][0] *= s0; yacc[0][nt][1] *= s0;
                yacc[0][nt][2] *= s1; yacc[0][nt][3] *= s1;
                yacc[1][nt][0] *= s2; yacc[1][nt][1] *= s2;
                yacc[1][nt][2] *= s3; yacc[1][nt][3] *= s3;
            }
        }
#pragma unroll 2
        for (int kst = 0; kst < 8; kst++) {
            int kk = kst * 8;
            uint32_t a[2][4];
#pragma unroll
            for (int mt = 0; mt < 2; mt++) {
                const float* ab = Ss + (r0 + 16 * mt + g) * TS + kk + t;
                a[mt][0] = __float_as_uint(ab[0]);
                a[mt][1] = __float_as_uint(ab[8 * TS]);
                a[mt][2] = __float_as_uint(ab[4]);
                a[mt][3] = __float_as_uint(ab[8 * TS + 4]);
            }
#pragma unroll
            for (int nt = 0; nt < 8; nt++) {
                const float* gb = Gs + (c0 + 8 * nt + g) * TS + kk + t;
                uint32_t b0 = __float_as_uint(gb[0]), b1 = __float_as_uint(gb[4]);
#pragma unroll
                for (int mt = 0; mt < 2; mt++)
                    mma_tf32(yacc[mt][nt], a[mt][0], a[mt][1], a[mt][2], a[mt][3], b0, b1);
            }
        }
    }

    __syncthreads();
#pragma unroll
    for (int mt = 0; mt < 2; mt++) {
        int ra = r0 + 16 * mt + g, rb = ra + 8;
        float ia = 1.f / rowl[ra], ib = 1.f / rowl[rb];
        float* Y0 = g_y + (size_t)(b * NN + q0 + ra) * ND + c0;
        float* Y1 = g_y + (size_t)(b * NN + q0 + rb) * ND + c0;
#pragma unroll
        for (int nt = 0; nt < 8; nt++) {
            *(float2*)(Y0 + 8 * nt + 2 * t) = make_float2(yacc[mt][nt][0] * ia, yacc[mt][nt][1] * ia);
            *(float2*)(Y1 + 8 * nt + 2 * t) = make_float2(yacc[mt][nt][2] * ib, yacc[mt][nt][3] * ib);
        }
    }
}

// ===========================================================================
// Output GEMM + residual (HMMA 3xTF32, pre-split B): out = x + y @ Wout
// ===========================================================================
__global__ __launch_bounds__(256, 2) void out_kernel(
    const float* __restrict__ x, const float* __restrict__ Wout, float* __restrict__ out)
{
    extern __shared__ float sm[];
    float*  As  = sm;
    float2* Bs2 = (float2*)(sm + 128 * TS);

    int tid = threadIdx.x, row0 = blockIdx.x * 128, col0 = blockIdx.y * 128;
    int lane = tid & 31, g = lane >> 2, t = lane & 3;
    int wid = tid >> 5, wr = wid >> 1, wc = wid & 1;
    int r0 = wr * 32, c0 = wc * 64;

    float acc[2][8][4];
#pragma unroll
    for (int mt = 0; mt < 2; mt++)
#pragma unroll
        for (int nt = 0; nt < 8; nt++)
#pragma unroll
            for (int i = 0; i < 4; i++) acc[mt][nt][i] = 0.f;

#pragma unroll 1
    for (int kc = 0; kc < 2; kc++) {
        int k0 = kc * 64;
        __syncthreads();
#pragma unroll
        for (int q = 0; q < 8; q++) {
            int li = q * 256 + tid, r = li >> 4, c = (li & 15) * 4;
            *(float4*)&As[r * TS + c] = *(const float4*)(g_y + (size_t)(row0 + r) * ND + k0 + c);
        }
#pragma unroll
        for (int q = 0; q < 8; q++) {
            int li = q * 256 + tid, n = li & 127, kq = li >> 7;
            float w0 = Wout[(size_t)(k0 + kq * 4 + 0) * NC + col0 + n];
            float w1 = Wout[(size_t)(k0 + kq * 4 + 1) * NC + col0 + n];
            float w2 = Wout[(size_t)(k0 + kq * 4 + 2) * NC + col0 + n];
            float w3 = Wout[(size_t)(k0 + kq * 4 + 3) * NC + col0 + n];
            float* dst = (float*)(Bs2 + n * PS2 + kq * 4);
            float h0 = tf32r(w0), h1 = tf32r(w1), h2 = tf32r(w2), h3 = tf32r(w3);
            *(float4*)(dst)     = make_float4(h0, tf32r(w0 - h0), h1, tf32r(w1 - h1));
            *(float4*)(dst + 4) = make_float4(h2, tf32r(w2 - h2), h3, tf32r(w3 - h3));
        }
        __syncthreads();
#pragma unroll 2
        for (int kst = 0; kst < 8; kst++) {
            int kk = kst * 8;
            uint32_t ah[2][4], al[2][4];
#pragma unroll
            for (int mt = 0; mt < 2; mt++) {
                const float* ab = As + (r0 + 16 * mt + g) * TS + kk + t;
                float v0 = ab[0], v1 = ab[8 * TS], v2 = ab[4], v3 = ab[8 * TS + 4];
                ah[mt][0] = f2tf32(v0); al[mt][0] = f2tf32(v0 - __uint_as_float(ah[mt][0]));
                ah[mt][1] = f2tf32(v1); al[mt][1] = f2tf32(v1 - __uint_as_float(ah[mt][1]));
                ah[mt][2] = f2tf32(v2); al[mt][2] = f2tf32(v2 - __uint_as_float(ah[mt][2]));
                ah[mt][3] = f2tf32(v3); al[mt][3] = f2tf32(v3 - __uint_as_float(ah[mt][3]));
            }
#pragma unroll
            for (int nt = 0; nt < 8; nt++) {
                const float2* bb = Bs2 + (c0 + 8 * nt + g) * PS2 + kk + t;
                float2 hv0 = bb[0], hv1 = bb[4];
                uint32_t bh0 = __float_as_uint(hv0.x), bl0 = __float_as_uint(hv0.y);
                uint32_t bh1 = __float_as_uint(hv1.x), bl1 = __float_as_uint(hv1.y);
#pragma unroll
                for (int mt = 0; mt < 2; mt++) {
                    mma_tf32(acc[mt][nt], ah[mt][0], ah[mt][1], ah[mt][2], ah[mt][3], bh0, bh1);
                    mma_tf32(acc[mt][nt], ah[mt][0], ah[mt][1], ah[mt][2], ah[mt][3], bl0, bl1);
                    mma_tf32(acc[mt][nt], al[mt][0], al[mt][1], al[mt][2], al[mt][3], bh0, bh1);
                }
            }
        }
    }
#pragma unroll
    for (int mt = 0; mt < 2; mt++) {
        int ra = row0 + r0 + 16 * mt + g;
        const float* X0 = x + (size_t)ra * NC + col0 + c0;
        const float* X1 = X0 + 8 * (size_t)NC;
        float* O0 = out + (size_t)ra * NC + col0 + c0;
        float* O1 = O0 + 8 * (size_t)NC;
#pragma unroll
        for (int nt = 0; nt < 8; nt++) {
            int cc = 8 * nt + 2 * t;
            float2 x0 = *(const float2*)(X0 + cc);
            float2 x1 = *(const float2*)(X1 + cc);
            *(float2*)(O0 + cc) = make_float2(acc[mt][nt][0] + x0.x, acc[mt][nt][1] + x0.y);
            *(float2*)(O1 + cc) = make_float2(acc[mt][nt][2] + x1.x, acc[mt][nt][3] + x1.y);
        }
    }
}

// ---------------------------------------------------------------------------
extern "C" void kernel_launch(void* const* d_in, const int* in_sizes, int n_in,
                              void* d_out, int out_size)
{
    const float* x  = (const float*)d_in[0];
    const float* Wt = (const float*)d_in[1];
    const float* Wp = (const float*)d_in[2];
    const float* Wg = (const float*)d_in[3];
    const float* Wo = (const float*)d_in[4];
    float* out      = (float*)d_out;

    const int SPLIT_SMEM = (128 * TS + 128 * PS2 * 2) * 4;   // 102400 B
    const int PV_SMEM    = PV_SMEM_FLOATS * 4;               // 73216 B
    cudaFuncSetAttribute(proj_kernel, cudaFuncAttributeMaxDynamicSharedMemorySize, SPLIT_SMEM);
    cudaFuncSetAttribute(qk_kernel,   cudaFuncAttributeMaxDynamicSharedMemorySize, SPLIT_SMEM);
    cudaFuncSetAttribute(pv_kernel,   cudaFuncAttributeMaxDynamicSharedMemorySize, PV_SMEM);
    cudaFuncSetAttribute(out_kernel,  cudaFuncAttributeMaxDynamicSharedMemorySize, SPLIT_SMEM);

    proj_kernel<<<dim3(256, 1, 3), 256, SPLIT_SMEM>>>(x, Wt, Wp, Wg);
    pool_kernel<<<(NB * NM * ND / 4 + 255) / 256, 256>>>();
    qk_kernel<<<dim3(32, 16, 8), 256, SPLIT_SMEM>>>();
    pv_kernel<<<dim3(32, 8), 256, PV_SMEM>>>();
    out_kernel<<<dim3(256, 2), 256, SPLIT_SMEM>>>(x, Wo, out);
}

// round 10
// speedup vs baseline: 1.1647x; 1.0208x over previous
#include <cuda_runtime.h>
#include <cstdint>

// NonLocalBlock B=8, N=4096, M=2048, C=256, d=128
#define NB 8
#define NN 4096
#define NM 2048
#define NC 256
#define ND 128

__device__ float g_theta[NB * NN * ND];
__device__ float g_phi  [NB * NN * ND];
__device__ float g_gg   [NB * NN * ND];
__device__ float g_phiP [NB * NM * ND];          // [b][m][d]
__device__ float g_gPt  [NB * ND * NM];          // [b][d][m]
__device__ float g_S    [NB * NN * NM];          // raw logits (256 MB)
__device__ float g_pmax [NB * NN * 32];          // per-row partial maxes (16 mtiles x 2 wc)
__device__ float g_y    [NB * NN * ND];

// ---------------------------------------------------------------------------
__device__ __forceinline__ uint32_t f2tf32(float v) {
    uint32_t r;
    asm("cvt.rna.tf32.f32 %0, %1;" : "=r"(r) : "f"(v));
    return r;
}
__device__ __forceinline__ float tf32r(float v) { return __uint_as_float(f2tf32(v)); }
__device__ __forceinline__ void mma_tf32(float (&d)[4],
                                         uint32_t a0, uint32_t a1, uint32_t a2, uint32_t a3,
                                         uint32_t b0, uint32_t b1) {
    asm volatile(
        "mma.sync.aligned.m16n8k8.row.col.f32.tf32.tf32.f32 "
        "{%0,%1,%2,%3}, {%4,%5,%6,%7}, {%8,%9}, {%0,%1,%2,%3};"
        : "+f"(d[0]), "+f"(d[1]), "+f"(d[2]), "+f"(d[3])
        : "r"(a0), "r"(a1), "r"(a2), "r"(a3), "r"(b0), "r"(b1));
}

#define TS 68      // plain fp32 tile stride (floats)
#define PS2 66     // pre-split tile stride (float2 units; 132 floats/row)

// ===========================================================================
// Projection GEMM (HMMA 3xTF32, pre-split B)  — unchanged from R8
// ===========================================================================
__global__ __launch_bounds__(256, 2) void proj_kernel(
    const float* __restrict__ x, const float* __restrict__ Wt,
    const float* __restrict__ Wp, const float* __restrict__ Wg)
{
    extern __shared__ float sm[];
    float*  As  = sm;
    float2* Bs2 = (float2*)(sm + 128 * TS);

    const float* W; float* out;
    if (blockIdx.z == 0)      { W = Wt; out = g_theta; }
    else if (blockIdx.z == 1) { W = Wp; out = g_phi; }
    else                      { W = Wg; out = g_gg; }

    int tid = threadIdx.x, row0 = blockIdx.x * 128;
    int lane = tid & 31, g = lane >> 2, t = lane & 3;
    int wid = tid >> 5, wr = wid >> 1, wc = wid & 1;
    int r0 = wr * 32, c0 = wc * 64;

    float acc[2][8][4];
#pragma unroll
    for (int mt = 0; mt < 2; mt++)
#pragma unroll
        for (int nt = 0; nt < 8; nt++)
#pragma unroll
            for (int i = 0; i < 4; i++) acc[mt][nt][i] = 0.f;

#pragma unroll 1
    for (int kc = 0; kc < 4; kc++) {
        int k0 = kc * 64;
        __syncthreads();
#pragma unroll
        for (int q = 0; q < 8; q++) {
            int li = q * 256 + tid, r = li >> 4, c = (li & 15) * 4;
            *(float4*)&As[r * TS + c] = *(const float4*)(x + (size_t)(row0 + r) * NC + k0 + c);
        }
#pragma unroll
        for (int q = 0; q < 8; q++) {
            int li = q * 256 + tid, n = li & 127, kq = li >> 7;
            float w0 = W[(size_t)(k0 + kq * 4 + 0) * ND + n];
            float w1 = W[(size_t)(k0 + kq * 4 + 1) * ND + n];
            float w2 = W[(size_t)(k0 + kq * 4 + 2) * ND + n];
            float w3 = W[(size_t)(k0 + kq * 4 + 3) * ND + n];
            float* dst = (float*)(Bs2 + n * PS2 + kq * 4);
            float h0 = tf32r(w0), h1 = tf32r(w1), h2 = tf32r(w2), h3 = tf32r(w3);
            *(float4*)(dst)     = make_float4(h0, tf32r(w0 - h0), h1, tf32r(w1 - h1));
            *(float4*)(dst + 4) = make_float4(h2, tf32r(w2 - h2), h3, tf32r(w3 - h3));
        }
        __syncthreads();
#pragma unroll 2
        for (int kst = 0; kst < 8; kst++) {
            int kk = kst * 8;
            uint32_t ah[2][4], al[2][4];
#pragma unroll
            for (int mt = 0; mt < 2; mt++) {
                const float* ab = As + (r0 + 16 * mt + g) * TS + kk + t;
                float v0 = ab[0], v1 = ab[8 * TS], v2 = ab[4], v3 = ab[8 * TS + 4];
                ah[mt][0] = f2tf32(v0); al[mt][0] = f2tf32(v0 - __uint_as_float(ah[mt][0]));
                ah[mt][1] = f2tf32(v1); al[mt][1] = f2tf32(v1 - __uint_as_float(ah[mt][1]));
                ah[mt][2] = f2tf32(v2); al[mt][2] = f2tf32(v2 - __uint_as_float(ah[mt][2]));
                ah[mt][3] = f2tf32(v3); al[mt][3] = f2tf32(v3 - __uint_as_float(ah[mt][3]));
            }
#pragma unroll
            for (int nt = 0; nt < 8; nt++) {
                const float2* bb = Bs2 + (c0 + 8 * nt + g) * PS2 + kk + t;
                float2 hv0 = bb[0], hv1 = bb[4];
                uint32_t bh0 = __float_as_uint(hv0.x), bl0 = __float_as_uint(hv0.y);
                uint32_t bh1 = __float_as_uint(hv1.x), bl1 = __float_as_uint(hv1.y);
#pragma unroll
                for (int mt = 0; mt < 2; mt++) {
                    mma_tf32(acc[mt][nt], ah[mt][0], ah[mt][1], ah[mt][2], ah[mt][3], bh0, bh1);
                    mma_tf32(acc[mt][nt], ah[mt][0], ah[mt][1], ah[mt][2], ah[mt][3], bl0, bl1);
                    mma_tf32(acc[mt][nt], al[mt][0], al[mt][1], al[mt][2], al[mt][3], bh0, bh1);
                }
            }
        }
    }
#pragma unroll
    for (int mt = 0; mt < 2; mt++) {
        float* O0 = out + (size_t)(row0 + r0 + 16 * mt + g) * ND + c0;
        float* O1 = O0 + 8 * (size_t)ND;
#pragma unroll
        for (int nt = 0; nt < 8; nt++) {
            *(float2*)(O0 + 8 * nt + 2 * t) = make_float2(acc[mt][nt][0], acc[mt][nt][1]);
            *(float2*)(O1 + 8 * nt + 2 * t) = make_float2(acc[mt][nt][2], acc[mt][nt][3]);
        }
    }
}

// ===========================================================================
// MaxPool(2): phi -> phiP, g -> gPt (transposed)
// ===========================================================================
__global__ __launch_bounds__(256) void pool_kernel()
{
    int idx4 = blockIdx.x * 256 + threadIdx.x;
    int total4 = NB * NM * ND / 4;
    if (idx4 >= total4) return;
    int d4 = idx4 % (ND / 4);
    int r  = (idx4 / (ND / 4)) % NM;
    int b  = idx4 / ((ND / 4) * NM);
    int src = ((b * NN + 2 * r) * ND) / 4 + d4;
    const float4* p = (const float4*)g_phi;
    const float4* g = (const float4*)g_gg;
    float4 a = p[src], a2 = p[src + ND / 4];
    float4 c = g[src], c2 = g[src + ND / 4];
    ((float4*)g_phiP)[idx4] = make_float4(fmaxf(a.x, a2.x), fmaxf(a.y, a2.y),
                                          fmaxf(a.z, a2.z), fmaxf(a.w, a2.w));
    int d0 = d4 * 4;
    g_gPt[(b * ND + d0 + 0) * NM + r] = fmaxf(c.x, c2.x);
    g_gPt[(b * ND + d0 + 1) * NM + r] = fmaxf(c.y, c2.y);
    g_gPt[(b * ND + d0 + 2) * NM + r] = fmaxf(c.z, c2.z);
    g_gPt[(b * ND + d0 + 3) * NM + r] = fmaxf(c.w, c2.w);
}

// ===========================================================================
// GEMM1 (HMMA 3xTF32): S_raw = theta @ phiP^T + per-row partial max epilogue
// ===========================================================================
__global__ __launch_bounds__(256, 2) void qk_kernel()
{
    extern __shared__ float sm[];
    float*  Qs  = sm;
    float2* Ks2 = (float2*)(sm + 128 * TS);

    int tid = threadIdx.x;
    int b = blockIdx.z, q0 = blockIdx.x * 128, m0 = blockIdx.y * 128;
    const float* Ap = g_theta + (size_t)(b * NN + q0) * ND;
    const float* Bp = g_phiP + (size_t)(b * NM + m0) * ND;

    int lane = tid & 31, g = lane >> 2, t = lane & 3;
    int wid = tid >> 5, wr = wid >> 1, wc = wid & 1;
    int r0 = wr * 32, c0 = wc * 64;

    float acc[2][8][4];
#pragma unroll
    for (int mt = 0; mt < 2; mt++)
#pragma unroll
        for (int nt = 0; nt < 8; nt++)
#pragma unroll
            for (int i = 0; i < 4; i++) acc[mt][nt][i] = 0.f;

#pragma unroll 1
    for (int kc = 0; kc < 2; kc++) {
        int k0 = kc * 64;
        __syncthreads();
#pragma unroll
        for (int q = 0; q < 8; q++) {
            int li = q * 256 + tid, r = li >> 4, c = (li & 15) * 4;
            *(float4*)&Qs[r * TS + c] = *(const float4*)(Ap + (size_t)r * ND + k0 + c);
            float4 v = *(const float4*)(Bp + (size_t)r * ND + k0 + c);
            float h0 = tf32r(v.x), h1 = tf32r(v.y), h2 = tf32r(v.z), h3 = tf32r(v.w);
            float* dst = (float*)(Ks2 + r * PS2 + c);
            *(float4*)(dst)     = make_float4(h0, tf32r(v.x - h0), h1, tf32r(v.y - h1));
            *(float4*)(dst + 4) = make_float4(h2, tf32r(v.z - h2), h3, tf32r(v.w - h3));
        }
        __syncthreads();
#pragma unroll 2
        for (int kst = 0; kst < 8; kst++) {
            int kk = kst * 8;
            uint32_t ah[2][4], al[2][4];
#pragma unroll
            for (int mt = 0; mt < 2; mt++) {
                const float* ab = Qs + (r0 + 16 * mt + g) * TS + kk + t;
                float v0 = ab[0], v1 = ab[8 * TS], v2 = ab[4], v3 = ab[8 * TS + 4];
                ah[mt][0] = f2tf32(v0); al[mt][0] = f2tf32(v0 - __uint_as_float(ah[mt][0]));
                ah[mt][1] = f2tf32(v1); al[mt][1] = f2tf32(v1 - __uint_as_float(ah[mt][1]));
                ah[mt][2] = f2tf32(v2); al[mt][2] = f2tf32(v2 - __uint_as_float(ah[mt][2]));
                ah[mt][3] = f2tf32(v3); al[mt][3] = f2tf32(v3 - __uint_as_float(ah[mt][3]));
            }
#pragma unroll
            for (int nt = 0; nt < 8; nt++) {
                const float2* kb = Ks2 + (c0 + 8 * nt + g) * PS2 + kk + t;
                float2 hv0 = kb[0], hv1 = kb[4];
                uint32_t bh0 = __float_as_uint(hv0.x), bl0 = __float_as_uint(hv0.y);
                uint32_t bh1 = __float_as_uint(hv1.x), bl1 = __float_as_uint(hv1.y);
#pragma unroll
                for (int mt = 0; mt < 2; mt++) {
                    mma_tf32(acc[mt][nt], ah[mt][0], ah[mt][1], ah[mt][2], ah[mt][3], bh0, bh1);
                    mma_tf32(acc[mt][nt], ah[mt][0], ah[mt][1], ah[mt][2], ah[mt][3], bl0, bl1);
                    mma_tf32(acc[mt][nt], al[mt][0], al[mt][1], al[mt][2], al[mt][3], bh0, bh1);
                }
            }
        }
    }
    // write RAW logits + per-row partial maxes of this 128-col slice
#pragma unroll
    for (int mt = 0; mt < 2; mt++) {
        size_t ra = (size_t)(b * NN + q0 + r0 + 16 * mt + g);
        float* So0 = g_S + ra * NM + m0 + c0;
        float* So1 = So0 + 8 * (size_t)NM;
        float mx0 = -1e30f, mx1 = -1e30f;
#pragma unroll
        for (int nt = 0; nt < 8; nt++) {
            *(float2*)(So0 + 8 * nt + 2 * t) = make_float2(acc[mt][nt][0], acc[mt][nt][1]);
            *(float2*)(So1 + 8 * nt + 2 * t) = make_float2(acc[mt][nt][2], acc[mt][nt][3]);
            mx0 = fmaxf(mx0, fmaxf(acc[mt][nt][0], acc[mt][nt][1]));
            mx1 = fmaxf(mx1, fmaxf(acc[mt][nt][2], acc[mt][nt][3]));
        }
        mx0 = fmaxf(mx0, __shfl_xor_sync(0xFFFFFFFF, mx0, 1));
        mx0 = fmaxf(mx0, __shfl_xor_sync(0xFFFFFFFF, mx0, 2));
        mx1 = fmaxf(mx1, __shfl_xor_sync(0xFFFFFFFF, mx1, 1));
        mx1 = fmaxf(mx1, __shfl_xor_sync(0xFFFFFFFF, mx1, 2));
        if (t == 0) {
            g_pmax[ra * 32 + blockIdx.y * 2 + wc]                  = mx0;
            g_pmax[(ra + 8) * 32 + blockIdx.y * 2 + wc]            = mx1;
        }
    }
}

// ===========================================================================
// Fused softmax + PV (HMMA 1xTF32), exact precomputed row max.
// Per chunk: 1 fused stage pass (exp + sums) + 1 MMA pass; 2 syncs.
// smem: Ss 128x68 (P tf32) | Gs 128x68 (G tf32) | rowm 128 | rowl 128
// ===========================================================================
#define PV_OFF_GS (128 * TS)
#define PV_OFF_ST (2 * 128 * TS)
#define PV_SMEM_FLOATS (PV_OFF_ST + 2 * 128)

__global__ __launch_bounds__(256, 2) void pv_kernel()
{
    extern __shared__ float sm[];
    float* Ss   = sm;
    float* Gs   = sm + PV_OFF_GS;
    float* rowm = sm + PV_OFF_ST;
    float* rowl = rowm + 128;

    int tid = threadIdx.x;
    int b = blockIdx.y, q0 = blockIdx.x * 128;
    const float* Sp = g_S + (size_t)(b * NN + q0) * NM;
    const float* Gp = g_gPt + (size_t)b * ND * NM;

    int lane = tid & 31, g = lane >> 2, t = lane & 3;
    int wid = tid >> 5, wr = wid >> 1, wc = wid & 1;
    int r0 = wr * 32, c0 = wc * 64;

    // exact row max from qk partials
    if (tid < 128) {
        const float* pm = g_pmax + (size_t)(b * NN + q0 + tid) * 32;
        float mx = pm[0];
#pragma unroll
        for (int j = 1; j < 32; j++) mx = fmaxf(mx, pm[j]);
        rowm[tid] = mx;
        rowl[tid] = 0.f;
    }

    float yacc[2][8][4];
#pragma unroll
    for (int mt = 0; mt < 2; mt++)
#pragma unroll
        for (int nt = 0; nt < 8; nt++)
#pragma unroll
            for (int i = 0; i < 4; i++) yacc[mt][nt][i] = 0.f;

#pragma unroll 1
    for (int ch = 0; ch < 32; ch++) {
        int m0 = ch * 64;
        __syncthreads();   // guards smem reuse; first iter also publishes rowm/rowl
        // Fused stage: S -> P = tf32(exp(S - rowm)) + partial sums; G -> tf32
#pragma unroll
        for (int q = 0; q < 8; q++) {
            int li = q * 256 + tid, r = li >> 4, c = (li & 15) * 4;
            float4 v = *(const float4*)(Sp + (size_t)r * NM + m0 + c);
            float nm = rowm[r];
            v.x = tf32r(__expf(v.x - nm)); v.y = tf32r(__expf(v.y - nm));
            v.z = tf32r(__expf(v.z - nm)); v.w = tf32r(__expf(v.w - nm));
            *(float4*)&Ss[r * TS + c] = v;
            float s = v.x + v.y + v.z + v.w;
            s += __shfl_xor_sync(0xFFFFFFFF, s, 1);
            s += __shfl_xor_sync(0xFFFFFFFF, s, 2);
            s += __shfl_xor_sync(0xFFFFFFFF, s, 4);
            s += __shfl_xor_sync(0xFFFFFFFF, s, 8);
            if ((tid & 15) == 0) rowl[r] += s;   // unique owner lane per row
            float4 w = *(const float4*)(Gp + (size_t)r * NM + m0 + c);
            *(float4*)&Gs[r * TS + c] = make_float4(tf32r(w.x), tf32r(w.y), tf32r(w.z), tf32r(w.w));
        }
        __syncthreads();
        // MMA over this chunk (K = 64), no rescale needed
#pragma unroll 2
        for (int kst = 0; kst < 8; kst++) {
            int kk = kst * 8;
            uint32_t a[2][4];
#pragma unroll
            for (int mt = 0; mt < 2; mt++) {
                const float* ab = Ss + (r0 + 16 * mt + g) * TS + kk + t;
                a[mt][0] = __float_as_uint(ab[0]);
                a[mt][1] = __float_as_uint(ab[8 * TS]);
                a[mt][2] = __float_as_uint(ab[4]);
                a[mt][3] = __float_as_uint(ab[8 * TS + 4]);
            }
#pragma unroll
            for (int nt = 0; nt < 8; nt++) {
                const float* gb = Gs + (c0 + 8 * nt + g) * TS + kk + t;
                uint32_t b0 = __float_as_uint(gb[0]), b1 = __float_as_uint(gb[4]);
#pragma unroll
                for (int mt = 0; mt < 2; mt++)
                    mma_tf32(yacc[mt][nt], a[mt][0], a[mt][1], a[mt][2], a[mt][3], b0, b1);
            }
        }
    }

    __syncthreads();
#pragma unroll
    for (int mt = 0; mt < 2; mt++) {
        int ra = r0 + 16 * mt + g, rb = ra + 8;
        float ia = 1.f / rowl[ra], ib = 1.f / rowl[rb];
        float* Y0 = g_y + (size_t)(b * NN + q0 + ra) * ND + c0;
        float* Y1 = g_y + (size_t)(b * NN + q0 + rb) * ND + c0;
#pragma unroll
        for (int nt = 0; nt < 8; nt++) {
            *(float2*)(Y0 + 8 * nt + 2 * t) = make_float2(yacc[mt][nt][0] * ia, yacc[mt][nt][1] * ia);
            *(float2*)(Y1 + 8 * nt + 2 * t) = make_float2(yacc[mt][nt][2] * ib, yacc[mt][nt][3] * ib);
        }
    }
}

// ===========================================================================
// Output GEMM + residual (HMMA 3xTF32, pre-split B) — unchanged from R8
// ===========================================================================
__global__ __launch_bounds__(256, 2) void out_kernel(
    const float* __restrict__ x, const float* __restrict__ Wout, float* __restrict__ out)
{
    extern __shared__ float sm[];
    float*  As  = sm;
    float2* Bs2 = (float2*)(sm + 128 * TS);

    int tid = threadIdx.x, row0 = blockIdx.x * 128, col0 = blockIdx.y * 128;
    int lane = tid & 31, g = lane >> 2, t = lane & 3;
    int wid = tid >> 5, wr = wid >> 1, wc = wid & 1;
    int r0 = wr * 32, c0 = wc * 64;

    float acc[2][8][4];
#pragma unroll
    for (int mt = 0; mt < 2; mt++)
#pragma unroll
        for (int nt = 0; nt < 8; nt++)
#pragma unroll
            for (int i = 0; i < 4; i++) acc[mt][nt][i] = 0.f;

#pragma unroll 1
    for (int kc = 0; kc < 2; kc++) {
        int k0 = kc * 64;
        __syncthreads();
#pragma unroll
        for (int q = 0; q < 8; q++) {
            int li = q * 256 + tid, r = li >> 4, c = (li & 15) * 4;
            *(float4*)&As[r * TS + c] = *(const float4*)(g_y + (size_t)(row0 + r) * ND + k0 + c);
        }
#pragma unroll
        for (int q = 0; q < 8; q++) {
            int li = q * 256 + tid, n = li & 127, kq = li >> 7;
            float w0 = Wout[(size_t)(k0 + kq * 4 + 0) * NC + col0 + n];
            float w1 = Wout[(size_t)(k0 + kq * 4 + 1) * NC + col0 + n];
            float w2 = Wout[(size_t)(k0 + kq * 4 + 2) * NC + col0 + n];
            float w3 = Wout[(size_t)(k0 + kq * 4 + 3) * NC + col0 + n];
            float* dst = (float*)(Bs2 + n * PS2 + kq * 4);
            float h0 = tf32r(w0), h1 = tf32r(w1), h2 = tf32r(w2), h3 = tf32r(w3);
            *(float4*)(dst)     = make_float4(h0, tf32r(w0 - h0), h1, tf32r(w1 - h1));
            *(float4*)(dst + 4) = make_float4(h2, tf32r(w2 - h2), h3, tf32r(w3 - h3));
        }
        __syncthreads();
#pragma unroll 2
        for (int kst = 0; kst < 8; kst++) {
            int kk = kst * 8;
            uint32_t ah[2][4], al[2][4];
#pragma unroll
            for (int mt = 0; mt < 2; mt++) {
                const float* ab = As + (r0 + 16 * mt + g) * TS + kk + t;
                float v0 = ab[0], v1 = ab[8 * TS], v2 = ab[4], v3 = ab[8 * TS + 4];
                ah[mt][0] = f2tf32(v0); al[mt][0] = f2tf32(v0 - __uint_as_float(ah[mt][0]));
                ah[mt][1] = f2tf32(v1); al[mt][1] = f2tf32(v1 - __uint_as_float(ah[mt][1]));
                ah[mt][2] = f2tf32(v2); al[mt][2] = f2tf32(v2 - __uint_as_float(ah[mt][2]));
                ah[mt][3] = f2tf32(v3); al[mt][3] = f2tf32(v3 - __uint_as_float(ah[mt][3]));
            }
#pragma unroll
            for (int nt = 0; nt < 8; nt++) {
                const float2* bb = Bs2 + (c0 + 8 * nt + g) * PS2 + kk + t;
                float2 hv0 = bb[0], hv1 = bb[4];
                uint32_t bh0 = __float_as_uint(hv0.x), bl0 = __float_as_uint(hv0.y);
                uint32_t bh1 = __float_as_uint(hv1.x), bl1 = __float_as_uint(hv1.y);
#pragma unroll
                for (int mt = 0; mt < 2; mt++) {
                    mma_tf32(acc[mt][nt], ah[mt][0], ah[mt][1], ah[mt][2], ah[mt][3], bh0, bh1);
                    mma_tf32(acc[mt][nt], ah[mt][0], ah[mt][1], ah[mt][2], ah[mt][3], bl0, bl1);
                    mma_tf32(acc[mt][nt], al[mt][0], al[mt][1], al[mt][2], al[mt][3], bh0, bh1);
                }
            }
        }
    }
#pragma unroll
    for (int mt = 0; mt < 2; mt++) {
        int ra = row0 + r0 + 16 * mt + g;
        const float* X0 = x + (size_t)ra * NC + col0 + c0;
        const float* X1 = X0 + 8 * (size_t)NC;
        float* O0 = out + (size_t)ra * NC + col0 + c0;
        float* O1 = O0 + 8 * (size_t)NC;
#pragma unroll
        for (int nt = 0; nt < 8; nt++) {
            int cc = 8 * nt + 2 * t;
            float2 x0 = *(const float2*)(X0 + cc);
            float2 x1 = *(const float2*)(X1 + cc);
            *(float2*)(O0 + cc) = make_float2(acc[mt][nt][0] + x0.x, acc[mt][nt][1] + x0.y);
            *(float2*)(O1 + cc) = make_float2(acc[mt][nt][2] + x1.x, acc[mt][nt][3] + x1.y);
        }
    }
}

// ---------------------------------------------------------------------------
extern "C" void kernel_launch(void* const* d_in, const int* in_sizes, int n_in,
                              void* d_out, int out_size)
{
    const float* x  = (const float*)d_in[0];
    const float* Wt = (const float*)d_in[1];
    const float* Wp = (const float*)d_in[2];
    const float* Wg = (const float*)d_in[3];
    const float* Wo = (const float*)d_in[4];
    float* out      = (float*)d_out;

    const int SPLIT_SMEM = (128 * TS + 128 * PS2 * 2) * 4;   // 102400 B
    const int PV_SMEM    = PV_SMEM_FLOATS * 4;               // 70656 B
    cudaFuncSetAttribute(proj_kernel, cudaFuncAttributeMaxDynamicSharedMemorySize, SPLIT_SMEM);
    cudaFuncSetAttribute(qk_kernel,   cudaFuncAttributeMaxDynamicSharedMemorySize, SPLIT_SMEM);
    cudaFuncSetAttribute(pv_kernel,   cudaFuncAttributeMaxDynamicSharedMemorySize, PV_SMEM);
    cudaFuncSetAttribute(out_kernel,  cudaFuncAttributeMaxDynamicSharedMemorySize, SPLIT_SMEM);

    proj_kernel<<<dim3(256, 1, 3), 256, SPLIT_SMEM>>>(x, Wt, Wp, Wg);
    pool_kernel<<<(NB * NM * ND / 4 + 255) / 256, 256>>>();
    qk_kernel<<<dim3(32, 16, 8), 256, SPLIT_SMEM>>>();
    pv_kernel<<<dim3(32, 8), 256, PV_SMEM>>>();
    out_kernel<<<dim3(256, 2), 256, SPLIT_SMEM>>>(x, Wo, out);
}

// round 11
// speedup vs baseline: 1.1779x; 1.0114x over previous
#include <cuda_runtime.h>
#include <cstdint>

// NonLocalBlock B=8, N=4096, M=2048, C=256, d=128
#define NB 8
#define NN 4096
#define NM 2048
#define NC 256
#define ND 128

__device__ float g_theta[NB * NN * ND];
__device__ float g_phi  [NB * NN * ND];
__device__ float g_gg   [NB * NN * ND];
__device__ float g_phiP [NB * NM * ND];          // [b][m][d]
__device__ float g_gPt  [NB * ND * NM];          // [b][d][m], tf32-rounded
__device__ float g_S    [NB * NN * NM];          // raw logits (256 MB)
__device__ float g_pmax [NB * NN * 32];          // per-row partial maxes
__device__ float g_y    [NB * NN * ND];

// ---------------------------------------------------------------------------
__device__ __forceinline__ uint32_t f2tf32(float v) {
    uint32_t r;
    asm("cvt.rna.tf32.f32 %0, %1;" : "=r"(r) : "f"(v));
    return r;
}
__device__ __forceinline__ float tf32r(float v) { return __uint_as_float(f2tf32(v)); }
__device__ __forceinline__ void mma_tf32(float (&d)[4],
                                         uint32_t a0, uint32_t a1, uint32_t a2, uint32_t a3,
                                         uint32_t b0, uint32_t b1) {
    asm volatile(
        "mma.sync.aligned.m16n8k8.row.col.f32.tf32.tf32.f32 "
        "{%0,%1,%2,%3}, {%4,%5,%6,%7}, {%8,%9}, {%0,%1,%2,%3};"
        : "+f"(d[0]), "+f"(d[1]), "+f"(d[2]), "+f"(d[3])
        : "r"(a0), "r"(a1), "r"(a2), "r"(a3), "r"(b0), "r"(b1));
}
__device__ __forceinline__ uint32_t smem_u32(const void* p) {
    uint32_t a;
    asm("{ .reg .u64 t; cvta.to.shared.u64 t, %1; cvt.u32.u64 %0, t; }" : "=r"(a) : "l"(p));
    return a;
}
__device__ __forceinline__ void cp_async16(uint32_t dst, const void* src) {
    asm volatile("cp.async.cg.shared.global [%0], [%1], 16;" :: "r"(dst), "l"(src) : "memory");
}
#define CP_COMMIT() asm volatile("cp.async.commit_group;" ::: "memory")
#define CP_WAIT1()  asm volatile("cp.async.wait_group 1;" ::: "memory")

#define TS 68      // plain fp32 tile stride (floats)
#define PS2 66     // pre-split tile stride (float2 units)

// ===========================================================================
// Projection GEMM (HMMA 3xTF32, pre-split B) — unchanged from R9
// ===========================================================================
__global__ __launch_bounds__(256, 2) void proj_kernel(
    const float* __restrict__ x, const float* __restrict__ Wt,
    const float* __restrict__ Wp, const float* __restrict__ Wg)
{
    extern __shared__ float sm[];
    float*  As  = sm;
    float2* Bs2 = (float2*)(sm + 128 * TS);

    const float* W; float* out;
    if (blockIdx.z == 0)      { W = Wt; out = g_theta; }
    else if (blockIdx.z == 1) { W = Wp; out = g_phi; }
    else                      { W = Wg; out = g_gg; }

    int tid = threadIdx.x, row0 = blockIdx.x * 128;
    int lane = tid & 31, g = lane >> 2, t = lane & 3;
    int wid = tid >> 5, wr = wid >> 1, wc = wid & 1;
    int r0 = wr * 32, c0 = wc * 64;

    float acc[2][8][4];
#pragma unroll
    for (int mt = 0; mt < 2; mt++)
#pragma unroll
        for (int nt = 0; nt < 8; nt++)
#pragma unroll
            for (int i = 0; i < 4; i++) acc[mt][nt][i] = 0.f;

#pragma unroll 1
    for (int kc = 0; kc < 4; kc++) {
        int k0 = kc * 64;
        __syncthreads();
#pragma unroll
        for (int q = 0; q < 8; q++) {
            int li = q * 256 + tid, r = li >> 4, c = (li & 15) * 4;
            *(float4*)&As[r * TS + c] = *(const float4*)(x + (size_t)(row0 + r) * NC + k0 + c);
        }
#pragma unroll
        for (int q = 0; q < 8; q++) {
            int li = q * 256 + tid, n = li & 127, kq = li >> 7;
            float w0 = W[(size_t)(k0 + kq * 4 + 0) * ND + n];
            float w1 = W[(size_t)(k0 + kq * 4 + 1) * ND + n];
            float w2 = W[(size_t)(k0 + kq * 4 + 2) * ND + n];
            float w3 = W[(size_t)(k0 + kq * 4 + 3) * ND + n];
            float* dst = (float*)(Bs2 + n * PS2 + kq * 4);
            float h0 = tf32r(w0), h1 = tf32r(w1), h2 = tf32r(w2), h3 = tf32r(w3);
            *(float4*)(dst)     = make_float4(h0, tf32r(w0 - h0), h1, tf32r(w1 - h1));
            *(float4*)(dst + 4) = make_float4(h2, tf32r(w2 - h2), h3, tf32r(w3 - h3));
        }
        __syncthreads();
#pragma unroll 2
        for (int kst = 0; kst < 8; kst++) {
            int kk = kst * 8;
            uint32_t ah[2][4], al[2][4];
#pragma unroll
            for (int mt = 0; mt < 2; mt++) {
                const float* ab = As + (r0 + 16 * mt + g) * TS + kk + t;
                float v0 = ab[0], v1 = ab[8 * TS], v2 = ab[4], v3 = ab[8 * TS + 4];
                ah[mt][0] = f2tf32(v0); al[mt][0] = f2tf32(v0 - __uint_as_float(ah[mt][0]));
                ah[mt][1] = f2tf32(v1); al[mt][1] = f2tf32(v1 - __uint_as_float(ah[mt][1]));
                ah[mt][2] = f2tf32(v2); al[mt][2] = f2tf32(v2 - __uint_as_float(ah[mt][2]));
                ah[mt][3] = f2tf32(v3); al[mt][3] = f2tf32(v3 - __uint_as_float(ah[mt][3]));
            }
#pragma unroll
            for (int nt = 0; nt < 8; nt++) {
                const float2* bb = Bs2 + (c0 + 8 * nt + g) * PS2 + kk + t;
                float2 hv0 = bb[0], hv1 = bb[4];
                uint32_t bh0 = __float_as_uint(hv0.x), bl0 = __float_as_uint(hv0.y);
                uint32_t bh1 = __float_as_uint(hv1.x), bl1 = __float_as_uint(hv1.y);
#pragma unroll
                for (int mt = 0; mt < 2; mt++) {
                    mma_tf32(acc[mt][nt], ah[mt][0], ah[mt][1], ah[mt][2], ah[mt][3], bh0, bh1);
                    mma_tf32(acc[mt][nt], ah[mt][0], ah[mt][1], ah[mt][2], ah[mt][3], bl0, bl1);
                    mma_tf32(acc[mt][nt], al[mt][0], al[mt][1], al[mt][2], al[mt][3], bh0, bh1);
                }
            }
        }
    }
#pragma unroll
    for (int mt = 0; mt < 2; mt++) {
        float* O0 = out + (size_t)(row0 + r0 + 16 * mt + g) * ND + c0;
        float* O1 = O0 + 8 * (size_t)ND;
#pragma unroll
        for (int nt = 0; nt < 8; nt++) {
            *(float2*)(O0 + 8 * nt + 2 * t) = make_float2(acc[mt][nt][0], acc[mt][nt][1]);
            *(float2*)(O1 + 8 * nt + 2 * t) = make_float2(acc[mt][nt][2], acc[mt][nt][3]);
        }
    }
}

// ===========================================================================
// MaxPool(2): phi -> phiP, g -> gPt (transposed, TF32-ROUNDED for pv cp.async)
// ===========================================================================
__global__ __launch_bounds__(256) void pool_kernel()
{
    int idx4 = blockIdx.x * 256 + threadIdx.x;
    int total4 = NB * NM * ND / 4;
    if (idx4 >= total4) return;
    int d4 = idx4 % (ND / 4);
    int r  = (idx4 / (ND / 4)) % NM;
    int b  = idx4 / ((ND / 4) * NM);
    int src = ((b * NN + 2 * r) * ND) / 4 + d4;
    const float4* p = (const float4*)g_phi;
    const float4* g = (const float4*)g_gg;
    float4 a = p[src], a2 = p[src + ND / 4];
    float4 c = g[src], c2 = g[src + ND / 4];
    ((float4*)g_phiP)[idx4] = make_float4(fmaxf(a.x, a2.x), fmaxf(a.y, a2.y),
                                          fmaxf(a.z, a2.z), fmaxf(a.w, a2.w));
    int d0 = d4 * 4;
    g_gPt[(b * ND + d0 + 0) * NM + r] = tf32r(fmaxf(c.x, c2.x));
    g_gPt[(b * ND + d0 + 1) * NM + r] = tf32r(fmaxf(c.y, c2.y));
    g_gPt[(b * ND + d0 + 2) * NM + r] = tf32r(fmaxf(c.z, c2.z));
    g_gPt[(b * ND + d0 + 3) * NM + r] = tf32r(fmaxf(c.w, c2.w));
}

// ===========================================================================
// GEMM1 (HMMA 3xTF32): S_raw = theta @ phiP^T + partial-max epilogue
// (unchanged from R9)
// ===========================================================================
__global__ __launch_bounds__(256, 2) void qk_kernel()
{
    extern __shared__ float sm[];
    float*  Qs  = sm;
    float2* Ks2 = (float2*)(sm + 128 * TS);

    int tid = threadIdx.x;
    int b = blockIdx.z, q0 = blockIdx.x * 128, m0 = blockIdx.y * 128;
    const float* Ap = g_theta + (size_t)(b * NN + q0) * ND;
    const float* Bp = g_phiP + (size_t)(b * NM + m0) * ND;

    int lane = tid & 31, g = lane >> 2, t = lane & 3;
    int wid = tid >> 5, wr = wid >> 1, wc = wid & 1;
    int r0 = wr * 32, c0 = wc * 64;

    float acc[2][8][4];
#pragma unroll
    for (int mt = 0; mt < 2; mt++)
#pragma unroll
        for (int nt = 0; nt < 8; nt++)
#pragma unroll
            for (int i = 0; i < 4; i++) acc[mt][nt][i] = 0.f;

#pragma unroll 1
    for (int kc = 0; kc < 2; kc++) {
        int k0 = kc * 64;
        __syncthreads();
#pragma unroll
        for (int q = 0; q < 8; q++) {
            int li = q * 256 + tid, r = li >> 4, c = (li & 15) * 4;
            *(float4*)&Qs[r * TS + c] = *(const float4*)(Ap + (size_t)r * ND + k0 + c);
            float4 v = *(const float4*)(Bp + (size_t)r * ND + k0 + c);
            float h0 = tf32r(v.x), h1 = tf32r(v.y), h2 = tf32r(v.z), h3 = tf32r(v.w);
            float* dst = (float*)(Ks2 + r * PS2 + c);
            *(float4*)(dst)     = make_float4(h0, tf32r(v.x - h0), h1, tf32r(v.y - h1));
            *(float4*)(dst + 4) = make_float4(h2, tf32r(v.z - h2), h3, tf32r(v.w - h3));
        }
        __syncthreads();
#pragma unroll 2
        for (int kst = 0; kst < 8; kst++) {
            int kk = kst * 8;
            uint32_t ah[2][4], al[2][4];
#pragma unroll
            for (int mt = 0; mt < 2; mt++) {
                const float* ab = Qs + (r0 + 16 * mt + g) * TS + kk + t;
                float v0 = ab[0], v1 = ab[8 * TS], v2 = ab[4], v3 = ab[8 * TS + 4];
                ah[mt][0] = f2tf32(v0); al[mt][0] = f2tf32(v0 - __uint_as_float(ah[mt][0]));
                ah[mt][1] = f2tf32(v1); al[mt][1] = f2tf32(v1 - __uint_as_float(ah[mt][1]));
                ah[mt][2] = f2tf32(v2); al[mt][2] = f2tf32(v2 - __uint_as_float(ah[mt][2]));
                ah[mt][3] = f2tf32(v3); al[mt][3] = f2tf32(v3 - __uint_as_float(ah[mt][3]));
            }
#pragma unroll
            for (int nt = 0; nt < 8; nt++) {
                const float2* kb = Ks2 + (c0 + 8 * nt + g) * PS2 + kk + t;
                float2 hv0 = kb[0], hv1 = kb[4];
                uint32_t bh0 = __float_as_uint(hv0.x), bl0 = __float_as_uint(hv0.y);
                uint32_t bh1 = __float_as_uint(hv1.x), bl1 = __float_as_uint(hv1.y);
#pragma unroll
                for (int mt = 0; mt < 2; mt++) {
                    mma_tf32(acc[mt][nt], ah[mt][0], ah[mt][1], ah[mt][2], ah[mt][3], bh0, bh1);
                    mma_tf32(acc[mt][nt], ah[mt][0], ah[mt][1], ah[mt][2], ah[mt][3], bl0, bl1);
                    mma_tf32(acc[mt][nt], al[mt][0], al[mt][1], al[mt][2], al[mt][3], bh0, bh1);
                }
            }
        }
    }
#pragma unroll
    for (int mt = 0; mt < 2; mt++) {
        size_t ra = (size_t)(b * NN + q0 + r0 + 16 * mt + g);
        float* So0 = g_S + ra * NM + m0 + c0;
        float* So1 = So0 + 8 * (size_t)NM;
        float mx0 = -1e30f, mx1 = -1e30f;
#pragma unroll
        for (int nt = 0; nt < 8; nt++) {
            *(float2*)(So0 + 8 * nt + 2 * t) = make_float2(acc[mt][nt][0], acc[mt][nt][1]);
            *(float2*)(So1 + 8 * nt + 2 * t) = make_float2(acc[mt][nt][2], acc[mt][nt][3]);
            mx0 = fmaxf(mx0, fmaxf(acc[mt][nt][0], acc[mt][nt][1]));
            mx1 = fmaxf(mx1, fmaxf(acc[mt][nt][2], acc[mt][nt][3]));
        }
        mx0 = fmaxf(mx0, __shfl_xor_sync(0xFFFFFFFF, mx0, 1));
        mx0 = fmaxf(mx0, __shfl_xor_sync(0xFFFFFFFF, mx0, 2));
        mx1 = fmaxf(mx1, __shfl_xor_sync(0xFFFFFFFF, mx1, 1));
        mx1 = fmaxf(mx1, __shfl_xor_sync(0xFFFFFFFF, mx1, 2));
        if (t == 0) {
            g_pmax[ra * 32 + blockIdx.y * 2 + wc]       = mx0;
            g_pmax[(ra + 8) * 32 + blockIdx.y * 2 + wc] = mx1;
        }
    }
}

// ===========================================================================
// Fused softmax + PV (HMMA 1xTF32), cp.async pipeline:
// S double-buffered (prefetch 2 ahead), G single-buffered (prefetch 1 ahead,
// committed in its own group ahead of S so wait_group(1) retires {G[ch],S[ch]}).
// smem: Ss[2] 128x68 | Gs 128x68 | rowm 128 | rowl 128  = 105472 B (2 CTA/SM)
// ===========================================================================
#define PV_OFF_G  (2 * 128 * TS)
#define PV_OFF_ST (3 * 128 * TS)
#define PV_SMEM_FLOATS (PV_OFF_ST + 2 * 128)

__global__ __launch_bounds__(256, 2) void pv_kernel()
{
    extern __shared__ float sm[];
    float* Gs   = sm + PV_OFF_G;
    float* rowm = sm + PV_OFF_ST;
    float* rowl = rowm + 128;

    int tid = threadIdx.x;
    int b = blockIdx.y, q0 = blockIdx.x * 128;
    const float* Sp = g_S + (size_t)(b * NN + q0) * NM;
    const float* Gp = g_gPt + (size_t)b * ND * NM;

    int lane = tid & 31, g = lane >> 2, t = lane & 3;
    int wid = tid >> 5, wr = wid >> 1, wc = wid & 1;
    int r0 = wr * 32, c0 = wc * 64;

    uint32_t sbase = smem_u32(sm);
    // per-thread copy slot (8 x 16B each for S and G)
    int cr = tid >> 4, cc = (tid & 15) * 4;   // row base, col

    // exact row max from qk partials
    if (tid < 128) {
        const float* pm = g_pmax + (size_t)(b * NN + q0 + tid) * 32;
        float mx = pm[0];
#pragma unroll
        for (int j = 1; j < 32; j++) mx = fmaxf(mx, pm[j]);
        rowm[tid] = mx;
        rowl[tid] = 0.f;
    }

    // Prologue: group A0 = {G[0], S[0]}, group B0 = {S[1]}
#pragma unroll
    for (int q = 0; q < 8; q++) {
        int r = q * 16 + cr;
        cp_async16(sbase + PV_OFF_G * 4 + (r * TS + cc) * 4, Gp + (size_t)r * NM + cc);
        cp_async16(sbase + (r * TS + cc) * 4, Sp + (size_t)r * NM + cc);
    }
    CP_COMMIT();
#pragma unroll
    for (int q = 0; q < 8; q++) {
        int r = q * 16 + cr;
        cp_async16(sbase + (128 * TS + r * TS + cc) * 4, Sp + (size_t)r * NM + 64 + cc);
    }
    CP_COMMIT();

    float yacc[2][8][4];
#pragma unroll
    for (int mt = 0; mt < 2; mt++)
#pragma unroll
        for (int nt = 0; nt < 8; nt++)
#pragma unroll
            for (int i = 0; i < 4; i++) yacc[mt][nt][i] = 0.f;

#pragma unroll 1
    for (int ch = 0; ch < 32; ch++) {
        int cur = ch & 1;
        float* Ss = sm + cur * 128 * TS;

        CP_WAIT1();          // {G[ch], S[ch]} arrived ({S[ch+1]} may be pending)
        __syncthreads();

        // exp pass in place: S -> P = tf32(exp(S - rowm)) + row sums
#pragma unroll
        for (int q = 0; q < 8; q++) {
            int li = q * 256 + tid, r = li >> 4, c = (li & 15) * 4;
            float4 v = *(float4*)&Ss[r * TS + c];
            float nm = rowm[r];
            v.x = tf32r(__expf(v.x - nm)); v.y = tf32r(__expf(v.y - nm));
            v.z = tf32r(__expf(v.z - nm)); v.w = tf32r(__expf(v.w - nm));
            *(float4*)&Ss[r * TS + c] = v;
            float s = v.x + v.y + v.z + v.w;
            s += __shfl_xor_sync(0xFFFFFFFF, s, 1);
            s += __shfl_xor_sync(0xFFFFFFFF, s, 2);
            s += __shfl_xor_sync(0xFFFFFFFF, s, 4);
            s += __shfl_xor_sync(0xFFFFFFFF, s, 8);
            if ((tid & 15) == 0) rowl[r] += s;
        }
        __syncthreads();

        // MMA pass (K = 64)
#pragma unroll 2
        for (int kst = 0; kst < 8; kst++) {
            int kk = kst * 8;
            uint32_t a[2][4];
#pragma unroll
            for (int mt = 0; mt < 2; mt++) {
                const float* ab = Ss + (r0 + 16 * mt + g) * TS + kk + t;
                a[mt][0] = __float_as_uint(ab[0]);
                a[mt][1] = __float_as_uint(ab[8 * TS]);
                a[mt][2] = __float_as_uint(ab[4]);
                a[mt][3] = __float_as_uint(ab[8 * TS + 4]);
            }
#pragma unroll
            for (int nt = 0; nt < 8; nt++) {
                const float* gb = Gs + (c0 + 8 * nt + g) * TS + kk + t;
                uint32_t b0 = __float_as_uint(gb[0]), b1 = __float_as_uint(gb[4]);
#pragma unroll
                for (int mt = 0; mt < 2; mt++)
                    mma_tf32(yacc[mt][nt], a[mt][0], a[mt][1], a[mt][2], a[mt][3], b0, b1);
            }
        }
        __syncthreads();   // MMA done: Gs and Ss[cur] free for prefetch

        // Prefetch: group {G[ch+1]} then group {S[ch+2]} (always commit both)
        if (ch + 1 < 32) {
            int m1 = (ch + 1) * 64;
#pragma unroll
            for (int q = 0; q < 8; q++) {
                int r = q * 16 + cr;
                cp_async16(sbase + PV_OFF_G * 4 + (r * TS + cc) * 4,
                           Gp + (size_t)r * NM + m1 + cc);
            }
        }
        CP_COMMIT();
        if (ch + 2 < 32) {
            int m2 = (ch + 2) * 64;
#pragma unroll
            for (int q = 0; q < 8; q++) {
                int r = q * 16 + cr;
                cp_async16(sbase + (cur * 128 * TS + r * TS + cc) * 4,
                           Sp + (size_t)r * NM + m2 + cc);
            }
        }
        CP_COMMIT();
    }

    __syncthreads();
#pragma unroll
    for (int mt = 0; mt < 2; mt++) {
        int ra = r0 + 16 * mt + g, rb = ra + 8;
        float ia = 1.f / rowl[ra], ib = 1.f / rowl[rb];
        float* Y0 = g_y + (size_t)(b * NN + q0 + ra) * ND + c0;
        float* Y1 = g_y + (size_t)(b * NN + q0 + rb) * ND + c0;
#pragma unroll
        for (int nt = 0; nt < 8; nt++) {
            *(float2*)(Y0 + 8 * nt + 2 * t) = make_float2(yacc[mt][nt][0] * ia, yacc[mt][nt][1] * ia);
            *(float2*)(Y1 + 8 * nt + 2 * t) = make_float2(yacc[mt][nt][2] * ib, yacc[mt][nt][3] * ib);
        }
    }
}

// ===========================================================================
// Output GEMM + residual (HMMA 3xTF32, pre-split B) — unchanged from R9
// ===========================================================================
__global__ __launch_bounds__(256, 2) void out_kernel(
    const float* __restrict__ x, const float* __restrict__ Wout, float* __restrict__ out)
{
    extern __shared__ float sm[];
    float*  As  = sm;
    float2* Bs2 = (float2*)(sm + 128 * TS);

    int tid = threadIdx.x, row0 = blockIdx.x * 128, col0 = blockIdx.y * 128;
    int lane = tid & 31, g = lane >> 2, t = lane & 3;
    int wid = tid >> 5, wr = wid >> 1, wc = wid & 1;
    int r0 = wr * 32, c0 = wc * 64;

    float acc[2][8][4];
#pragma unroll
    for (int mt = 0; mt < 2; mt++)
#pragma unroll
        for (int nt = 0; nt < 8; nt++)
#pragma unroll
            for (int i = 0; i < 4; i++) acc[mt][nt][i] = 0.f;

#pragma unroll 1
    for (int kc = 0; kc < 2; kc++) {
        int k0 = kc * 64;
        __syncthreads();
#pragma unroll
        for (int q = 0; q < 8; q++) {
            int li = q * 256 + tid, r = li >> 4, c = (li & 15) * 4;
            *(float4*)&As[r * TS + c] = *(const float4*)(g_y + (size_t)(row0 + r) * ND + k0 + c);
        }
#pragma unroll
        for (int q = 0; q < 8; q++) {
            int li = q * 256 + tid, n = li & 127, kq = li >> 7;
            float w0 = Wout[(size_t)(k0 + kq * 4 + 0) * NC + col0 + n];
            float w1 = Wout[(size_t)(k0 + kq * 4 + 1) * NC + col0 + n];
            float w2 = Wout[(size_t)(k0 + kq * 4 + 2) * NC + col0 + n];
            float w3 = Wout[(size_t)(k0 + kq * 4 + 3) * NC + col0 + n];
            float* dst = (float*)(Bs2 + n * PS2 + kq * 4);
            float h0 = tf32r(w0), h1 = tf32r(w1), h2 = tf32r(w2), h3 = tf32r(w3);
            *(float4*)(dst)     = make_float4(h0, tf32r(w0 - h0), h1, tf32r(w1 - h1));
            *(float4*)(dst + 4) = make_float4(h2, tf32r(w2 - h2), h3, tf32r(w3 - h3));
        }
        __syncthreads();
#pragma unroll 2
        for (int kst = 0; kst < 8; kst++) {
            int kk = kst * 8;
            uint32_t ah[2][4], al[2][4];
#pragma unroll
            for (int mt = 0; mt < 2; mt++) {
                const float* ab = As + (r0 + 16 * mt + g) * TS + kk + t;
                float v0 = ab[0], v1 = ab[8 * TS], v2 = ab[4], v3 = ab[8 * TS + 4];
                ah[mt][0] = f2tf32(v0); al[mt][0] = f2tf32(v0 - __uint_as_float(ah[mt][0]));
                ah[mt][1] = f2tf32(v1); al[mt][1] = f2tf32(v1 - __uint_as_float(ah[mt][1]));
                ah[mt][2] = f2tf32(v2); al[mt][2] = f2tf32(v2 - __uint_as_float(ah[mt][2]));
                ah[mt][3] = f2tf32(v3); al[mt][3] = f2tf32(v3 - __uint_as_float(ah[mt][3]));
            }
#pragma unroll
            for (int nt = 0; nt < 8; nt++) {
                const float2* bb = Bs2 + (c0 + 8 * nt + g) * PS2 + kk + t;
                float2 hv0 = bb[0], hv1 = bb[4];
                uint32_t bh0 = __float_as_uint(hv0.x), bl0 = __float_as_uint(hv0.y);
                uint32_t bh1 = __float_as_uint(hv1.x), bl1 = __float_as_uint(hv1.y);
#pragma unroll
                for (int mt = 0; mt < 2; mt++) {
                    mma_tf32(acc[mt][nt], ah[mt][0], ah[mt][1], ah[mt][2], ah[mt][3], bh0, bh1);
                    mma_tf32(acc[mt][nt], ah[mt][0], ah[mt][1], ah[mt][2], ah[mt][3], bl0, bl1);
                    mma_tf32(acc[mt][nt], al[mt][0], al[mt][1], al[mt][2], al[mt][3], bh0, bh1);
                }
            }
        }
    }
#pragma unroll
    for (int mt = 0; mt < 2; mt++) {
        int ra = row0 + r0 + 16 * mt + g;
        const float* X0 = x + (size_t)ra * NC + col0 + c0;
        const float* X1 = X0 + 8 * (size_t)NC;
        float* O0 = out + (size_t)ra * NC + col0 + c0;
        float* O1 = O0 + 8 * (size_t)NC;
#pragma unroll
        for (int nt = 0; nt < 8; nt++) {
            int cc = 8 * nt + 2 * t;
            float2 x0 = *(const float2*)(X0 + cc);
            float2 x1 = *(const float2*)(X1 + cc);
            *(float2*)(O0 + cc) = make_float2(acc[mt][nt][0] + x0.x, acc[mt][nt][1] + x0.y);
            *(float2*)(O1 + cc) = make_float2(acc[mt][nt][2] + x1.x, acc[mt][nt][3] + x1.y);
        }
    }
}

// ---------------------------------------------------------------------------
extern "C" void kernel_launch(void* const* d_in, const int* in_sizes, int n_in,
                              void* d_out, int out_size)
{
    const float* x  = (const float*)d_in[0];
    const float* Wt = (const float*)d_in[1];
    const float* Wp = (const float*)d_in[2];
    const float* Wg = (const float*)d_in[3];
    const float* Wo = (const float*)d_in[4];
    float* out      = (float*)d_out;

    const int SPLIT_SMEM = (128 * TS + 128 * PS2 * 2) * 4;   // 102400 B
    const int PV_SMEM    = PV_SMEM_FLOATS * 4;               // 105472 B
    cudaFuncSetAttribute(proj_kernel, cudaFuncAttributeMaxDynamicSharedMemorySize, SPLIT_SMEM);
    cudaFuncSetAttribute(qk_kernel,   cudaFuncAttributeMaxDynamicSharedMemorySize, SPLIT_SMEM);
    cudaFuncSetAttribute(pv_kernel,   cudaFuncAttributeMaxDynamicSharedMemorySize, PV_SMEM);
    cudaFuncSetAttribute(out_kernel,  cudaFuncAttributeMaxDynamicSharedMemorySize, SPLIT_SMEM);

    proj_kernel<<<dim3(256, 1, 3), 256, SPLIT_SMEM>>>(x, Wt, Wp, Wg);
    pool_kernel<<<(NB * NM * ND / 4 + 255) / 256, 256>>>();
    qk_kernel<<<dim3(32, 16, 8), 256, SPLIT_SMEM>>>();
    pv_kernel<<<dim3(32, 8), 256, PV_SMEM>>>();
    out_kernel<<<dim3(256, 2), 256, SPLIT_SMEM>>>(x, Wo, out);
}

// round 12
// speedup vs baseline: 1.2914x; 1.0964x over previous
#include <cuda_runtime.h>
#include <cuda_fp16.h>
#include <cstdint>

// NonLocalBlock B=8, N=4096, M=2048, C=256, d=128
#define NB 8
#define NN 4096
#define NM 2048
#define NC 256
#define ND 128

__device__ float  g_theta[NB * NN * ND];
__device__ float  g_phi  [NB * NN * ND];
__device__ float  g_gg   [NB * NN * ND];
__device__ float  g_phiP [NB * NM * ND];         // [b][m][d]
__device__ __half g_gPt  [NB * ND * NM];         // [b][d][m], fp16
__device__ float  g_S    [NB * NN * NM];         // raw logits (256 MB)
__device__ float  g_pmax [NB * NN * 32];         // per-row partial maxes
__device__ float  g_y    [NB * NN * ND];

// ---------------------------------------------------------------------------
__device__ __forceinline__ uint32_t f2tf32(float v) {
    uint32_t r;
    asm("cvt.rna.tf32.f32 %0, %1;" : "=r"(r) : "f"(v));
    return r;
}
__device__ __forceinline__ float tf32r(float v) { return __uint_as_float(f2tf32(v)); }
__device__ __forceinline__ void mma_tf32(float (&d)[4],
                                         uint32_t a0, uint32_t a1, uint32_t a2, uint32_t a3,
                                         uint32_t b0, uint32_t b1) {
    asm volatile(
        "mma.sync.aligned.m16n8k8.row.col.f32.tf32.tf32.f32 "
        "{%0,%1,%2,%3}, {%4,%5,%6,%7}, {%8,%9}, {%0,%1,%2,%3};"
        : "+f"(d[0]), "+f"(d[1]), "+f"(d[2]), "+f"(d[3])
        : "r"(a0), "r"(a1), "r"(a2), "r"(a3), "r"(b0), "r"(b1));
}
__device__ __forceinline__ void mma_f16(float (&d)[4],
                                        uint32_t a0, uint32_t a1, uint32_t a2, uint32_t a3,
                                        uint32_t b0, uint32_t b1) {
    asm volatile(
        "mma.sync.aligned.m16n8k16.row.col.f32.f16.f16.f32 "
        "{%0,%1,%2,%3}, {%4,%5,%6,%7}, {%8,%9}, {%0,%1,%2,%3};"
        : "+f"(d[0]), "+f"(d[1]), "+f"(d[2]), "+f"(d[3])
        : "r"(a0), "r"(a1), "r"(a2), "r"(a3), "r"(b0), "r"(b1));
}
__device__ __forceinline__ uint32_t smem_u32(const void* p) {
    uint32_t a;
    asm("{ .reg .u64 t; cvta.to.shared.u64 t, %1; cvt.u32.u64 %0, t; }" : "=r"(a) : "l"(p));
    return a;
}
__device__ __forceinline__ void cp_async16(uint32_t dst, const void* src) {
    asm volatile("cp.async.cg.shared.global [%0], [%1], 16;" :: "r"(dst), "l"(src) : "memory");
}
#define CP_COMMIT() asm volatile("cp.async.commit_group;" ::: "memory")
#define CP_WAIT1()  asm volatile("cp.async.wait_group 1;" ::: "memory")

#define TS 68      // plain fp32 tile stride (floats)
#define PS2 66     // pre-split tile stride (float2 units)

// ===========================================================================
// Projection GEMM (HMMA 3xTF32, pre-split B) — unchanged
// ===========================================================================
__global__ __launch_bounds__(256, 2) void proj_kernel(
    const float* __restrict__ x, const float* __restrict__ Wt,
    const float* __restrict__ Wp, const float* __restrict__ Wg)
{
    extern __shared__ float sm[];
    float*  As  = sm;
    float2* Bs2 = (float2*)(sm + 128 * TS);

    const float* W; float* out;
    if (blockIdx.z == 0)      { W = Wt; out = g_theta; }
    else if (blockIdx.z == 1) { W = Wp; out = g_phi; }
    else                      { W = Wg; out = g_gg; }

    int tid = threadIdx.x, row0 = blockIdx.x * 128;
    int lane = tid & 31, g = lane >> 2, t = lane & 3;
    int wid = tid >> 5, wr = wid >> 1, wc = wid & 1;
    int r0 = wr * 32, c0 = wc * 64;

    float acc[2][8][4];
#pragma unroll
    for (int mt = 0; mt < 2; mt++)
#pragma unroll
        for (int nt = 0; nt < 8; nt++)
#pragma unroll
            for (int i = 0; i < 4; i++) acc[mt][nt][i] = 0.f;

#pragma unroll 1
    for (int kc = 0; kc < 4; kc++) {
        int k0 = kc * 64;
        __syncthreads();
#pragma unroll
        for (int q = 0; q < 8; q++) {
            int li = q * 256 + tid, r = li >> 4, c = (li & 15) * 4;
            *(float4*)&As[r * TS + c] = *(const float4*)(x + (size_t)(row0 + r) * NC + k0 + c);
        }
#pragma unroll
        for (int q = 0; q < 8; q++) {
            int li = q * 256 + tid, n = li & 127, kq = li >> 7;
            float w0 = W[(size_t)(k0 + kq * 4 + 0) * ND + n];
            float w1 = W[(size_t)(k0 + kq * 4 + 1) * ND + n];
            float w2 = W[(size_t)(k0 + kq * 4 + 2) * ND + n];
            float w3 = W[(size_t)(k0 + kq * 4 + 3) * ND + n];
            float* dst = (float*)(Bs2 + n * PS2 + kq * 4);
            float h0 = tf32r(w0), h1 = tf32r(w1), h2 = tf32r(w2), h3 = tf32r(w3);
            *(float4*)(dst)     = make_float4(h0, tf32r(w0 - h0), h1, tf32r(w1 - h1));
            *(float4*)(dst + 4) = make_float4(h2, tf32r(w2 - h2), h3, tf32r(w3 - h3));
        }
        __syncthreads();
#pragma unroll 2
        for (int kst = 0; kst < 8; kst++) {
            int kk = kst * 8;
            uint32_t ah[2][4], al[2][4];
#pragma unroll
            for (int mt = 0; mt < 2; mt++) {
                const float* ab = As + (r0 + 16 * mt + g) * TS + kk + t;
                float v0 = ab[0], v1 = ab[8 * TS], v2 = ab[4], v3 = ab[8 * TS + 4];
                ah[mt][0] = f2tf32(v0); al[mt][0] = f2tf32(v0 - __uint_as_float(ah[mt][0]));
                ah[mt][1] = f2tf32(v1); al[mt][1] = f2tf32(v1 - __uint_as_float(ah[mt][1]));
                ah[mt][2] = f2tf32(v2); al[mt][2] = f2tf32(v2 - __uint_as_float(ah[mt][2]));
                ah[mt][3] = f2tf32(v3); al[mt][3] = f2tf32(v3 - __uint_as_float(ah[mt][3]));
            }
#pragma unroll
            for (int nt = 0; nt < 8; nt++) {
                const float2* bb = Bs2 + (c0 + 8 * nt + g) * PS2 + kk + t;
                float2 hv0 = bb[0], hv1 = bb[4];
                uint32_t bh0 = __float_as_uint(hv0.x), bl0 = __float_as_uint(hv0.y);
                uint32_t bh1 = __float_as_uint(hv1.x), bl1 = __float_as_uint(hv1.y);
#pragma unroll
                for (int mt = 0; mt < 2; mt++) {
                    mma_tf32(acc[mt][nt], ah[mt][0], ah[mt][1], ah[mt][2], ah[mt][3], bh0, bh1);
                    mma_tf32(acc[mt][nt], ah[mt][0], ah[mt][1], ah[mt][2], ah[mt][3], bl0, bl1);
                    mma_tf32(acc[mt][nt], al[mt][0], al[mt][1], al[mt][2], al[mt][3], bh0, bh1);
                }
            }
        }
    }
#pragma unroll
    for (int mt = 0; mt < 2; mt++) {
        float* O0 = out + (size_t)(row0 + r0 + 16 * mt + g) * ND + c0;
        float* O1 = O0 + 8 * (size_t)ND;
#pragma unroll
        for (int nt = 0; nt < 8; nt++) {
            *(float2*)(O0 + 8 * nt + 2 * t) = make_float2(acc[mt][nt][0], acc[mt][nt][1]);
            *(float2*)(O1 + 8 * nt + 2 * t) = make_float2(acc[mt][nt][2], acc[mt][nt][3]);
        }
    }
}

// ===========================================================================
// MaxPool(2): phi -> phiP (fp32), g -> gPt (transposed, fp16)
// ===========================================================================
__global__ __launch_bounds__(256) void pool_kernel()
{
    int idx4 = blockIdx.x * 256 + threadIdx.x;
    int total4 = NB * NM * ND / 4;
    if (idx4 >= total4) return;
    int d4 = idx4 % (ND / 4);
    int r  = (idx4 / (ND / 4)) % NM;
    int b  = idx4 / ((ND / 4) * NM);
    int src = ((b * NN + 2 * r) * ND) / 4 + d4;
    const float4* p = (const float4*)g_phi;
    const float4* g = (const float4*)g_gg;
    float4 a = p[src], a2 = p[src + ND / 4];
    float4 c = g[src], c2 = g[src + ND / 4];
    ((float4*)g_phiP)[idx4] = make_float4(fmaxf(a.x, a2.x), fmaxf(a.y, a2.y),
                                          fmaxf(a.z, a2.z), fmaxf(a.w, a2.w));
    int d0 = d4 * 4;
    g_gPt[(b * ND + d0 + 0) * NM + r] = __float2half(fmaxf(c.x, c2.x));
    g_gPt[(b * ND + d0 + 1) * NM + r] = __float2half(fmaxf(c.y, c2.y));
    g_gPt[(b * ND + d0 + 2) * NM + r] = __float2half(fmaxf(c.z, c2.z));
    g_gPt[(b * ND + d0 + 3) * NM + r] = __float2half(fmaxf(c.w, c2.w));
}

// ===========================================================================
// GEMM1 (HMMA 3xTF32): S_raw = theta @ phiP^T + partial-max epilogue
// (unchanged)
// ===========================================================================
__global__ __launch_bounds__(256, 2) void qk_kernel()
{
    extern __shared__ float sm[];
    float*  Qs  = sm;
    float2* Ks2 = (float2*)(sm + 128 * TS);

    int tid = threadIdx.x;
    int b = blockIdx.z, q0 = blockIdx.x * 128, m0 = blockIdx.y * 128;
    const float* Ap = g_theta + (size_t)(b * NN + q0) * ND;
    const float* Bp = g_phiP + (size_t)(b * NM + m0) * ND;

    int lane = tid & 31, g = lane >> 2, t = lane & 3;
    int wid = tid >> 5, wr = wid >> 1, wc = wid & 1;
    int r0 = wr * 32, c0 = wc * 64;

    float acc[2][8][4];
#pragma unroll
    for (int mt = 0; mt < 2; mt++)
#pragma unroll
        for (int nt = 0; nt < 8; nt++)
#pragma unroll
            for (int i = 0; i < 4; i++) acc[mt][nt][i] = 0.f;

#pragma unroll 1
    for (int kc = 0; kc < 2; kc++) {
        int k0 = kc * 64;
        __syncthreads();
#pragma unroll
        for (int q = 0; q < 8; q++) {
            int li = q * 256 + tid, r = li >> 4, c = (li & 15) * 4;
            *(float4*)&Qs[r * TS + c] = *(const float4*)(Ap + (size_t)r * ND + k0 + c);
            float4 v = *(const float4*)(Bp + (size_t)r * ND + k0 + c);
            float h0 = tf32r(v.x), h1 = tf32r(v.y), h2 = tf32r(v.z), h3 = tf32r(v.w);
            float* dst = (float*)(Ks2 + r * PS2 + c);
            *(float4*)(dst)     = make_float4(h0, tf32r(v.x - h0), h1, tf32r(v.y - h1));
            *(float4*)(dst + 4) = make_float4(h2, tf32r(v.z - h2), h3, tf32r(v.w - h3));
        }
        __syncthreads();
#pragma unroll 2
        for (int kst = 0; kst < 8; kst++) {
            int kk = kst * 8;
            uint32_t ah[2][4], al[2][4];
#pragma unroll
            for (int mt = 0; mt < 2; mt++) {
                const float* ab = Qs + (r0 + 16 * mt + g) * TS + kk + t;
                float v0 = ab[0], v1 = ab[8 * TS], v2 = ab[4], v3 = ab[8 * TS + 4];
                ah[mt][0] = f2tf32(v0); al[mt][0] = f2tf32(v0 - __uint_as_float(ah[mt][0]));
                ah[mt][1] = f2tf32(v1); al[mt][1] = f2tf32(v1 - __uint_as_float(ah[mt][1]));
                ah[mt][2] = f2tf32(v2); al[mt][2] = f2tf32(v2 - __uint_as_float(ah[mt][2]));
                ah[mt][3] = f2tf32(v3); al[mt][3] = f2tf32(v3 - __uint_as_float(ah[mt][3]));
            }
#pragma unroll
            for (int nt = 0; nt < 8; nt++) {
                const float2* kb = Ks2 + (c0 + 8 * nt + g) * PS2 + kk + t;
                float2 hv0 = kb[0], hv1 = kb[4];
                uint32_t bh0 = __float_as_uint(hv0.x), bl0 = __float_as_uint(hv0.y);
                uint32_t bh1 = __float_as_uint(hv1.x), bl1 = __float_as_uint(hv1.y);
#pragma unroll
                for (int mt = 0; mt < 2; mt++) {
                    mma_tf32(acc[mt][nt], ah[mt][0], ah[mt][1], ah[mt][2], ah[mt][3], bh0, bh1);
                    mma_tf32(acc[mt][nt], ah[mt][0], ah[mt][1], ah[mt][2], ah[mt][3], bl0, bl1);
                    mma_tf32(acc[mt][nt], al[mt][0], al[mt][1], al[mt][2], al[mt][3], bh0, bh1);
                }
            }
        }
    }
#pragma unroll
    for (int mt = 0; mt < 2; mt++) {
        size_t ra = (size_t)(b * NN + q0 + r0 + 16 * mt + g);
        float* So0 = g_S + ra * NM + m0 + c0;
        float* So1 = So0 + 8 * (size_t)NM;
        float mx0 = -1e30f, mx1 = -1e30f;
#pragma unroll
        for (int nt = 0; nt < 8; nt++) {
            *(float2*)(So0 + 8 * nt + 2 * t) = make_float2(acc[mt][nt][0], acc[mt][nt][1]);
            *(float2*)(So1 + 8 * nt + 2 * t) = make_float2(acc[mt][nt][2], acc[mt][nt][3]);
            mx0 = fmaxf(mx0, fmaxf(acc[mt][nt][0], acc[mt][nt][1]));
            mx1 = fmaxf(mx1, fmaxf(acc[mt][nt][2], acc[mt][nt][3]));
        }
        mx0 = fmaxf(mx0, __shfl_xor_sync(0xFFFFFFFF, mx0, 1));
        mx0 = fmaxf(mx0, __shfl_xor_sync(0xFFFFFFFF, mx0, 2));
        mx1 = fmaxf(mx1, __shfl_xor_sync(0xFFFFFFFF, mx1, 1));
        mx1 = fmaxf(mx1, __shfl_xor_sync(0xFFFFFFFF, mx1, 2));
        if (t == 0) {
            g_pmax[ra * 32 + blockIdx.y * 2 + wc]       = mx0;
            g_pmax[(ra + 8) * 32 + blockIdx.y * 2 + wc] = mx1;
        }
    }
}

// ===========================================================================
// Fused softmax + PV (HMMA fp16 m16n8k16):
//  - S fp32 cp.async double-buffered; S[ch+2] prefetch issued BEFORE MMA
//    (P lives in its own buffer, so Ss is free during MMA)
//  - P: half2-packed in Ps (stride 36 u32, conflict-free)
//  - G: global fp16, raw cp.async into Gs (stride 36 u32)
// smem: Ss[2] 128x68 f32 | Ps 128x36 u32 | Gs 128x36 u32 | stats = 107.5 KB
// ===========================================================================
#define PSTR 36
#define PV_OFF_PS (2 * 128 * TS)
#define PV_OFF_GS (PV_OFF_PS + 128 * PSTR)
#define PV_OFF_ST (PV_OFF_GS + 128 * PSTR)
#define PV_SMEM_FLOATS (PV_OFF_ST + 2 * 128)

__global__ __launch_bounds__(256, 2) void pv_kernel()
{
    extern __shared__ float sm[];
    uint32_t* Ps  = (uint32_t*)(sm + PV_OFF_PS);
    uint32_t* Gs  = (uint32_t*)(sm + PV_OFF_GS);
    float*   rowm = sm + PV_OFF_ST;
    float*   rowl = rowm + 128;

    int tid = threadIdx.x;
    int b = blockIdx.y, q0 = blockIdx.x * 128;
    const float*  Sp  = g_S + (size_t)(b * NN + q0) * NM;
    const __half* GpH = g_gPt + (size_t)b * ND * NM;

    int lane = tid & 31, g = lane >> 2, t = lane & 3;
    int wid = tid >> 5, wr = wid >> 1, wc = wid & 1;
    int r0 = wr * 32, c0 = wc * 64;

    uint32_t sbase = smem_u32(sm);
    int cr = tid >> 4, cc = (tid & 15) * 4;          // S copy slot
    int gr = tid >> 1, gs = (tid & 1) * 8;           // (unused helper)
    (void)gr; (void)gs;

    // exact row max from qk partials
    if (tid < 128) {
        const float* pm = g_pmax + (size_t)(b * NN + q0 + tid) * 32;
        float mx = pm[0];
#pragma unroll
        for (int j = 1; j < 32; j++) mx = fmaxf(mx, pm[j]);
        rowm[tid] = mx;
        rowl[tid] = 0.f;
    }

    // Prologue: group0 = {G0, S0}; group1 = {S1}
#pragma unroll
    for (int q = 0; q < 4; q++) {
        int idx = q * 256 + tid, r = idx >> 3, hs = (idx & 7) * 8;
        cp_async16(sbase + (PV_OFF_GS + r * PSTR) * 4 + hs * 2, GpH + (size_t)r * NM + hs);
    }
#pragma unroll
    for (int q = 0; q < 8; q++) {
        int r = q * 16 + cr;
        cp_async16(sbase + (r * TS + cc) * 4, Sp + (size_t)r * NM + cc);
    }
    CP_COMMIT();
#pragma unroll
    for (int q = 0; q < 8; q++) {
        int r = q * 16 + cr;
        cp_async16(sbase + (128 * TS + r * TS + cc) * 4, Sp + (size_t)r * NM + 64 + cc);
    }
    CP_COMMIT();

    float yacc[2][8][4];
#pragma unroll
    for (int mt = 0; mt < 2; mt++)
#pragma unroll
        for (int nt = 0; nt < 8; nt++)
#pragma unroll
            for (int i = 0; i < 4; i++) yacc[mt][nt][i] = 0.f;

    int erow = tid >> 1, ecol = (tid & 1) * 32;      // exp-pass ownership

#pragma unroll 1
    for (int ch = 0; ch < 32; ch++) {
        int cur = ch & 1;
        float* Ss = sm + cur * 128 * TS;

        CP_WAIT1();          // {G[ch], S[ch]} landed
        __syncthreads();

        // exp pass: one thread owns 32 cols of one row; register sum
        {
            float nm = rowm[erow];
            const float* src = Ss + erow * TS + ecol;
            uint32_t* dst = Ps + erow * PSTR + (ecol >> 1);
            float sum = 0.f;
#pragma unroll
            for (int j = 0; j < 8; j++) {
                float4 v = *(const float4*)(src + j * 4);
                float p0 = __expf(v.x - nm), p1 = __expf(v.y - nm);
                float p2 = __expf(v.z - nm), p3 = __expf(v.w - nm);
                sum += p0 + p1 + p2 + p3;
                __half2 h01 = __floats2half2_rn(p0, p1);
                __half2 h23 = __floats2half2_rn(p2, p3);
                dst[j * 2]     = *(uint32_t*)&h01;
                dst[j * 2 + 1] = *(uint32_t*)&h23;
            }
            sum += __shfl_xor_sync(0xFFFFFFFF, sum, 1);
            if ((tid & 1) == 0) rowl[erow] += sum;
        }
        __syncthreads();

        // S[ch+2] prefetch NOW (Ss[cur] free; MMA reads only Ps/Gs)
        if (ch + 2 < 32) {
            int m2 = (ch + 2) * 64;
#pragma unroll
            for (int q = 0; q < 8; q++) {
                int r = q * 16 + cr;
                cp_async16(sbase + (cur * 128 * TS + r * TS + cc) * 4,
                           Sp + (size_t)r * NM + m2 + cc);
            }
        }

        // MMA pass: K = 64 in 4 k16 steps
#pragma unroll
        for (int kst = 0; kst < 4; kst++) {
            int kh = kst * 8;
            uint32_t a[2][4];
#pragma unroll
            for (int mt = 0; mt < 2; mt++) {
                const uint32_t* ab = Ps + (r0 + 16 * mt + g) * PSTR + kh + t;
                a[mt][0] = ab[0];
                a[mt][1] = ab[8 * PSTR];
                a[mt][2] = ab[4];
                a[mt][3] = ab[8 * PSTR + 4];
            }
#pragma unroll
            for (int nt = 0; nt < 8; nt++) {
                const uint32_t* gb = Gs + (c0 + 8 * nt + g) * PSTR + kh + t;
                uint32_t b0 = gb[0], b1 = gb[4];
#pragma unroll
                for (int mt = 0; mt < 2; mt++)
                    mma_f16(yacc[mt][nt], a[mt][0], a[mt][1], a[mt][2], a[mt][3], b0, b1);
            }
        }
        __syncthreads();   // MMA done: Gs free

        // G[ch+1] prefetch; bundle {S[ch+2], G[ch+1]} in one group + empty
        if (ch + 1 < 32) {
            int m1 = (ch + 1) * 64;
#pragma unroll
            for (int q = 0; q < 4; q++) {
                int idx = q * 256 + tid, r = idx >> 3, hs = (idx & 7) * 8;
                cp_async16(sbase + (PV_OFF_GS + r * PSTR) * 4 + hs * 2,
                           GpH + (size_t)r * NM + m1 + hs);
            }
        }
        CP_COMMIT();
        CP_COMMIT();
    }

    __syncthreads();
#pragma unroll
    for (int mt = 0; mt < 2; mt++) {
        int ra = r0 + 16 * mt + g, rb = ra + 8;
        float ia = 1.f / rowl[ra], ib = 1.f / rowl[rb];
        float* Y0 = g_y + (size_t)(b * NN + q0 + ra) * ND + c0;
        float* Y1 = g_y + (size_t)(b * NN + q0 + rb) * ND + c0;
#pragma unroll
        for (int nt = 0; nt < 8; nt++) {
            *(float2*)(Y0 + 8 * nt + 2 * t) = make_float2(yacc[mt][nt][0] * ia, yacc[mt][nt][1] * ia);
            *(float2*)(Y1 + 8 * nt + 2 * t) = make_float2(yacc[mt][nt][2] * ib, yacc[mt][nt][3] * ib);
        }
    }
}

// ===========================================================================
// Output GEMM + residual (HMMA 3xTF32, pre-split B) — unchanged
// ===========================================================================
__global__ __launch_bounds__(256, 2) void out_kernel(
    const float* __restrict__ x, const float* __restrict__ Wout, float* __restrict__ out)
{
    extern __shared__ float sm[];
    float*  As  = sm;
    float2* Bs2 = (float2*)(sm + 128 * TS);

    int tid = threadIdx.x, row0 = blockIdx.x * 128, col0 = blockIdx.y * 128;
    int lane = tid & 31, g = lane >> 2, t = lane & 3;
    int wid = tid >> 5, wr = wid >> 1, wc = wid & 1;
    int r0 = wr * 32, c0 = wc * 64;

    float acc[2][8][4];
#pragma unroll
    for (int mt = 0; mt < 2; mt++)
#pragma unroll
        for (int nt = 0; nt < 8; nt++)
#pragma unroll
            for (int i = 0; i < 4; i++) acc[mt][nt][i] = 0.f;

#pragma unroll 1
    for (int kc = 0; kc < 2; kc++) {
        int k0 = kc * 64;
        __syncthreads();
#pragma unroll
        for (int q = 0; q < 8; q++) {
            int li = q * 256 + tid, r = li >> 4, c = (li & 15) * 4;
            *(float4*)&As[r * TS + c] = *(const float4*)(g_y + (size_t)(row0 + r) * ND + k0 + c);
        }
#pragma unroll
        for (int q = 0; q < 8; q++) {
            int li = q * 256 + tid, n = li & 127, kq = li >> 7;
            float w0 = Wout[(size_t)(k0 + kq * 4 + 0) * NC + col0 + n];
            float w1 = Wout[(size_t)(k0 + kq * 4 + 1) * NC + col0 + n];
            float w2 = Wout[(size_t)(k0 + kq * 4 + 2) * NC + col0 + n];
            float w3 = Wout[(size_t)(k0 + kq * 4 + 3) * NC + col0 + n];
            float* dst = (float*)(Bs2 + n * PS2 + kq * 4);
            float h0 = tf32r(w0), h1 = tf32r(w1), h2 = tf32r(w2), h3 = tf32r(w3);
            *(float4*)(dst)     = make_float4(h0, tf32r(w0 - h0), h1, tf32r(w1 - h1));
            *(float4*)(dst + 4) = make_float4(h2, tf32r(w2 - h2), h3, tf32r(w3 - h3));
        }
        __syncthreads();
#pragma unroll 2
        for (int kst = 0; kst < 8; kst++) {
            int kk = kst * 8;
            uint32_t ah[2][4], al[2][4];
#pragma unroll
            for (int mt = 0; mt < 2; mt++) {
                const float* ab = As + (r0 + 16 * mt + g) * TS + kk + t;
                float v0 = ab[0], v1 = ab[8 * TS], v2 = ab[4], v3 = ab[8 * TS + 4];
                ah[mt][0] = f2tf32(v0); al[mt][0] = f2tf32(v0 - __uint_as_float(ah[mt][0]));
                ah[mt][1] = f2tf32(v1); al[mt][1] = f2tf32(v1 - __uint_as_float(ah[mt][1]));
                ah[mt][2] = f2tf32(v2); al[mt][2] = f2tf32(v2 - __uint_as_float(ah[mt][2]));
                ah[mt][3] = f2tf32(v3); al[mt][3] = f2tf32(v3 - __uint_as_float(ah[mt][3]));
            }
#pragma unroll
            for (int nt = 0; nt < 8; nt++) {
                const float2* bb = Bs2 + (c0 + 8 * nt + g) * PS2 + kk + t;
                float2 hv0 = bb[0], hv1 = bb[4];
                uint32_t bh0 = __float_as_uint(hv0.x), bl0 = __float_as_uint(hv0.y);
                uint32_t bh1 = __float_as_uint(hv1.x), bl1 = __float_as_uint(hv1.y);
#pragma unroll
                for (int mt = 0; mt < 2; mt++) {
                    mma_tf32(acc[mt][nt], ah[mt][0], ah[mt][1], ah[mt][2], ah[mt][3], bh0, bh1);
                    mma_tf32(acc[mt][nt], ah[mt][0], ah[mt][1], ah[mt][2], ah[mt][3], bl0, bl1);
                    mma_tf32(acc[mt][nt], al[mt][0], al[mt][1], al[mt][2], al[mt][3], bh0, bh1);
                }
            }
        }
    }
#pragma unroll
    for (int mt = 0; mt < 2; mt++) {
        int ra = row0 + r0 + 16 * mt + g;
        const float* X0 = x + (size_t)ra * NC + col0 + c0;
        const float* X1 = X0 + 8 * (size_t)NC;
        float* O0 = out + (size_t)ra * NC + col0 + c0;
        float* O1 = O0 + 8 * (size_t)NC;
#pragma unroll
        for (int nt = 0; nt < 8; nt++) {
            int cc = 8 * nt + 2 * t;
            float2 x0 = *(const float2*)(X0 + cc);
            float2 x1 = *(const float2*)(X1 + cc);
            *(float2*)(O0 + cc) = make_float2(acc[mt][nt][0] + x0.x, acc[mt][nt][1] + x0.y);
            *(float2*)(O1 + cc) = make_float2(acc[mt][nt][2] + x1.x, acc[mt][nt][3] + x1.y);
        }
    }
}

// ---------------------------------------------------------------------------
extern "C" void kernel_launch(void* const* d_in, const int* in_sizes, int n_in,
                              void* d_out, int out_size)
{
    const float* x  = (const float*)d_in[0];
    const float* Wt = (const float*)d_in[1];
    const float* Wp = (const float*)d_in[2];
    const float* Wg = (const float*)d_in[3];
    const float* Wo = (const float*)d_in[4];
    float* out      = (float*)d_out;

    const int SPLIT_SMEM = (128 * TS + 128 * PS2 * 2) * 4;   // 102400 B
    const int PV_SMEM    = PV_SMEM_FLOATS * 4;               // 107520 B
    cudaFuncSetAttribute(proj_kernel, cudaFuncAttributeMaxDynamicSharedMemorySize, SPLIT_SMEM);
    cudaFuncSetAttribute(qk_kernel,   cudaFuncAttributeMaxDynamicSharedMemorySize, SPLIT_SMEM);
    cudaFuncSetAttribute(pv_kernel,   cudaFuncAttributeMaxDynamicSharedMemorySize, PV_SMEM);
    cudaFuncSetAttribute(out_kernel,  cudaFuncAttributeMaxDynamicSharedMemorySize, SPLIT_SMEM);

    proj_kernel<<<dim3(256, 1, 3), 256, SPLIT_SMEM>>>(x, Wt, Wp, Wg);
    pool_kernel<<<(NB * NM * ND / 4 + 255) / 256, 256>>>();
    qk_kernel<<<dim3(32, 16, 8), 256, SPLIT_SMEM>>>();
    pv_kernel<<<dim3(32, 8), 256, PV_SMEM>>>();
    out_kernel<<<dim3(256, 2), 256, SPLIT_SMEM>>>(x, Wo, out);
}

// round 13
// speedup vs baseline: 2.0462x; 1.5845x over previous
#include <cuda_runtime.h>
#include <cuda_fp16.h>
#include <cstdint>

// NonLocalBlock B=8, N=4096, M=2048, C=256, d=128
#define NB 8
#define NN 4096
#define NM 2048
#define NC 256
#define ND 128

__device__ float  g_theta[NB * NN * ND];
__device__ float  g_phi  [NB * NN * ND];
__device__ float  g_gg   [NB * NN * ND];
__device__ float  g_phiP [NB * NM * ND];         // [b][m][d]
__device__ __half g_gPt  [NB * ND * NM];         // [b][d][m], fp16
__device__ float  g_S    [NB * NN * NM];         // raw logits (256 MB)
__device__ float  g_pmax [NB * NN * 32];         // per-row partial maxes
__device__ float  g_y    [NB * NN * ND];

// ---------------------------------------------------------------------------
__device__ __forceinline__ void mma_f16(float (&d)[4],
                                        uint32_t a0, uint32_t a1, uint32_t a2, uint32_t a3,
                                        uint32_t b0, uint32_t b1) {
    asm volatile(
        "mma.sync.aligned.m16n8k16.row.col.f32.f16.f16.f32 "
        "{%0,%1,%2,%3}, {%4,%5,%6,%7}, {%8,%9}, {%0,%1,%2,%3};"
        : "+f"(d[0]), "+f"(d[1]), "+f"(d[2]), "+f"(d[3])
        : "r"(a0), "r"(a1), "r"(a2), "r"(a3), "r"(b0), "r"(b1));
}
__device__ __forceinline__ uint32_t smem_u32(const void* p) {
    uint32_t a;
    asm("{ .reg .u64 t; cvta.to.shared.u64 t, %1; cvt.u32.u64 %0, t; }" : "=r"(a) : "l"(p));
    return a;
}
__device__ __forceinline__ void cp_async16(uint32_t dst, const void* src) {
    asm volatile("cp.async.cg.shared.global [%0], [%1], 16;" :: "r"(dst), "l"(src) : "memory");
}
#define CP_COMMIT() asm volatile("cp.async.commit_group;" ::: "memory")
#define CP_WAIT1()  asm volatile("cp.async.wait_group 1;" ::: "memory")

__device__ __forceinline__ uint32_t h2pack(float a, float b) {
    __half2 h = __floats2half2_rn(a, b);
    return *(uint32_t*)&h;
}
// split 4 floats into hi(2xhalf2) and lo(2xhalf2)
__device__ __forceinline__ void split4(float4 v, uint2& hi, uint2& lo) {
    __half h0 = __float2half_rn(v.x), h1 = __float2half_rn(v.y);
    __half h2 = __float2half_rn(v.z), h3 = __float2half_rn(v.w);
    float l0 = v.x - __half2float(h0), l1 = v.y - __half2float(h1);
    float l2 = v.z - __half2float(h2), l3 = v.w - __half2float(h3);
    __half2 hh0 = __halves2half2(h0, h1), hh1 = __halves2half2(h2, h3);
    hi.x = *(uint32_t*)&hh0; hi.y = *(uint32_t*)&hh1;
    lo.x = h2pack(l0, l1);   lo.y = h2pack(l2, l3);
}

#define W36 36                   // split tile stride in u32 words
#define OFF_AH 0
#define OFF_AL (128 * W36)
#define OFF_BH (2 * 128 * W36)
#define OFF_BL (3 * 128 * W36)
#define GEMM_SMEM_U32 (4 * 128 * W36)   // 73728 B

// ===========================================================================
// Split-fp16 GEMM mainloop body (shared shape): warp tile 32x64, mt=2, nt=8,
// K chunk = 64 (4 k16 steps).
// ===========================================================================
#define GEMM_MAINLOOP(SMU)                                                     \
    _Pragma("unroll")                                                          \
    for (int kst = 0; kst < 4; kst++) {                                        \
        int kh = kst * 8;                                                      \
        uint32_t ah[2][4], al[2][4];                                           \
        _Pragma("unroll")                                                      \
        for (int mt = 0; mt < 2; mt++) {                                       \
            int base = (r0 + 16 * mt + g) * W36 + kh + t;                      \
            ah[mt][0] = SMU[OFF_AH + base];                                    \
            ah[mt][1] = SMU[OFF_AH + base + 8 * W36];                          \
            ah[mt][2] = SMU[OFF_AH + base + 4];                                \
            ah[mt][3] = SMU[OFF_AH + base + 8 * W36 + 4];                      \
            al[mt][0] = SMU[OFF_AL + base];                                    \
            al[mt][1] = SMU[OFF_AL + base + 8 * W36];                          \
            al[mt][2] = SMU[OFF_AL + base + 4];                                \
            al[mt][3] = SMU[OFF_AL + base + 8 * W36 + 4];                      \
        }                                                                      \
        _Pragma("unroll")                                                      \
        for (int nt = 0; nt < 8; nt++) {                                       \
            int gb = (c0 + 8 * nt + g) * W36 + kh + t;                         \
            uint32_t bh0 = SMU[OFF_BH + gb], bh1 = SMU[OFF_BH + gb + 4];       \
            uint32_t bl0 = SMU[OFF_BL + gb], bl1 = SMU[OFF_BL + gb + 4];       \
            _Pragma("unroll")                                                  \
            for (int mt = 0; mt < 2; mt++) {                                   \
                mma_f16(acc[mt][nt], ah[mt][0], ah[mt][1], ah[mt][2], ah[mt][3], bh0, bh1); \
                mma_f16(acc[mt][nt], ah[mt][0], ah[mt][1], ah[mt][2], ah[mt][3], bl0, bl1); \
                mma_f16(acc[mt][nt], al[mt][0], al[mt][1], al[mt][2], al[mt][3], bh0, bh1); \
            }                                                                  \
        }                                                                      \
    }

// ===========================================================================
// Projection GEMM (split-fp16): C[32768,128] = x[32768,256] @ W[256,128], x3
// ===========================================================================
__global__ __launch_bounds__(256, 2) void proj_kernel(
    const float* __restrict__ x, const float* __restrict__ Wt,
    const float* __restrict__ Wp, const float* __restrict__ Wg)
{
    extern __shared__ uint32_t smu[];

    const float* W; float* out;
    if (blockIdx.z == 0)      { W = Wt; out = g_theta; }
    else if (blockIdx.z == 1) { W = Wp; out = g_phi; }
    else                      { W = Wg; out = g_gg; }

    int tid = threadIdx.x, row0 = blockIdx.x * 128;
    int lane = tid & 31, g = lane >> 2, t = lane & 3;
    int wid = tid >> 5, wr = wid >> 1, wc = wid & 1;
    int r0 = wr * 32, c0 = wc * 64;

    float acc[2][8][4];
#pragma unroll
    for (int mt = 0; mt < 2; mt++)
#pragma unroll
        for (int nt = 0; nt < 8; nt++)
#pragma unroll
            for (int i = 0; i < 4; i++) acc[mt][nt][i] = 0.f;

#pragma unroll 1
    for (int kc = 0; kc < 4; kc++) {
        int k0 = kc * 64;
        __syncthreads();
        // A: x rows (contiguous k), split-pack
#pragma unroll
        for (int q = 0; q < 8; q++) {
            int li = q * 256 + tid, r = li >> 4, c = (li & 15) * 4;
            float4 v = *(const float4*)(x + (size_t)(row0 + r) * NC + k0 + c);
            uint2 hi, lo; split4(v, hi, lo);
            *(uint2*)&smu[OFF_AH + r * W36 + (c >> 1)] = hi;
            *(uint2*)&smu[OFF_AL + r * W36 + (c >> 1)] = lo;
        }
        // B: W[k][n] -> n-major split tiles
#pragma unroll
        for (int q = 0; q < 8; q++) {
            int li = q * 256 + tid, n = li & 127, kq = li >> 7;
            float4 v;
            v.x = W[(size_t)(k0 + kq * 4 + 0) * ND + n];
            v.y = W[(size_t)(k0 + kq * 4 + 1) * ND + n];
            v.z = W[(size_t)(k0 + kq * 4 + 2) * ND + n];
            v.w = W[(size_t)(k0 + kq * 4 + 3) * ND + n];
            uint2 hi, lo; split4(v, hi, lo);
            *(uint2*)&smu[OFF_BH + n * W36 + kq * 2] = hi;
            *(uint2*)&smu[OFF_BL + n * W36 + kq * 2] = lo;
        }
        __syncthreads();
        GEMM_MAINLOOP(smu)
    }
#pragma unroll
    for (int mt = 0; mt < 2; mt++) {
        float* O0 = out + (size_t)(row0 + r0 + 16 * mt + g) * ND + c0;
        float* O1 = O0 + 8 * (size_t)ND;
#pragma unroll
        for (int nt = 0; nt < 8; nt++) {
            *(float2*)(O0 + 8 * nt + 2 * t) = make_float2(acc[mt][nt][0], acc[mt][nt][1]);
            *(float2*)(O1 + 8 * nt + 2 * t) = make_float2(acc[mt][nt][2], acc[mt][nt][3]);
        }
    }
}

// ===========================================================================
// MaxPool(2): phi -> phiP (fp32), g -> gPt (transposed, fp16)
// ===========================================================================
__global__ __launch_bounds__(256) void pool_kernel()
{
    int idx4 = blockIdx.x * 256 + threadIdx.x;
    int total4 = NB * NM * ND / 4;
    if (idx4 >= total4) return;
    int d4 = idx4 % (ND / 4);
    int r  = (idx4 / (ND / 4)) % NM;
    int b  = idx4 / ((ND / 4) * NM);
    int src = ((b * NN + 2 * r) * ND) / 4 + d4;
    const float4* p = (const float4*)g_phi;
    const float4* g = (const float4*)g_gg;
    float4 a = p[src], a2 = p[src + ND / 4];
    float4 c = g[src], c2 = g[src + ND / 4];
    ((float4*)g_phiP)[idx4] = make_float4(fmaxf(a.x, a2.x), fmaxf(a.y, a2.y),
                                          fmaxf(a.z, a2.z), fmaxf(a.w, a2.w));
    int d0 = d4 * 4;
    g_gPt[(b * ND + d0 + 0) * NM + r] = __float2half(fmaxf(c.x, c2.x));
    g_gPt[(b * ND + d0 + 1) * NM + r] = __float2half(fmaxf(c.y, c2.y));
    g_gPt[(b * ND + d0 + 2) * NM + r] = __float2half(fmaxf(c.z, c2.z));
    g_gPt[(b * ND + d0 + 3) * NM + r] = __float2half(fmaxf(c.w, c2.w));
}

// ===========================================================================
// GEMM1 (split-fp16): S_raw = theta @ phiP^T + partial-max epilogue
// ===========================================================================
__global__ __launch_bounds__(256, 2) void qk_kernel()
{
    extern __shared__ uint32_t smu[];

    int tid = threadIdx.x;
    int b = blockIdx.z, q0 = blockIdx.x * 128, m0 = blockIdx.y * 128;
    const float* Ap = g_theta + (size_t)(b * NN + q0) * ND;
    const float* Bp = g_phiP + (size_t)(b * NM + m0) * ND;

    int lane = tid & 31, g = lane >> 2, t = lane & 3;
    int wid = tid >> 5, wr = wid >> 1, wc = wid & 1;
    int r0 = wr * 32, c0 = wc * 64;

    float acc[2][8][4];
#pragma unroll
    for (int mt = 0; mt < 2; mt++)
#pragma unroll
        for (int nt = 0; nt < 8; nt++)
#pragma unroll
            for (int i = 0; i < 4; i++) acc[mt][nt][i] = 0.f;

#pragma unroll 1
    for (int kc = 0; kc < 2; kc++) {
        int k0 = kc * 64;
        __syncthreads();
#pragma unroll
        for (int q = 0; q < 8; q++) {
            int li = q * 256 + tid, r = li >> 4, c = (li & 15) * 4;
            float4 va = *(const float4*)(Ap + (size_t)r * ND + k0 + c);
            uint2 hi, lo; split4(va, hi, lo);
            *(uint2*)&smu[OFF_AH + r * W36 + (c >> 1)] = hi;
            *(uint2*)&smu[OFF_AL + r * W36 + (c >> 1)] = lo;
            float4 vb = *(const float4*)(Bp + (size_t)r * ND + k0 + c);
            split4(vb, hi, lo);
            *(uint2*)&smu[OFF_BH + r * W36 + (c >> 1)] = hi;
            *(uint2*)&smu[OFF_BL + r * W36 + (c >> 1)] = lo;
        }
        __syncthreads();
        GEMM_MAINLOOP(smu)
    }
    // write RAW logits + per-row partial maxes
#pragma unroll
    for (int mt = 0; mt < 2; mt++) {
        size_t ra = (size_t)(b * NN + q0 + r0 + 16 * mt + g);
        float* So0 = g_S + ra * NM + m0 + c0;
        float* So1 = So0 + 8 * (size_t)NM;
        float mx0 = -1e30f, mx1 = -1e30f;
#pragma unroll
        for (int nt = 0; nt < 8; nt++) {
            *(float2*)(So0 + 8 * nt + 2 * t) = make_float2(acc[mt][nt][0], acc[mt][nt][1]);
            *(float2*)(So1 + 8 * nt + 2 * t) = make_float2(acc[mt][nt][2], acc[mt][nt][3]);
            mx0 = fmaxf(mx0, fmaxf(acc[mt][nt][0], acc[mt][nt][1]));
            mx1 = fmaxf(mx1, fmaxf(acc[mt][nt][2], acc[mt][nt][3]));
        }
        mx0 = fmaxf(mx0, __shfl_xor_sync(0xFFFFFFFF, mx0, 1));
        mx0 = fmaxf(mx0, __shfl_xor_sync(0xFFFFFFFF, mx0, 2));
        mx1 = fmaxf(mx1, __shfl_xor_sync(0xFFFFFFFF, mx1, 1));
        mx1 = fmaxf(mx1, __shfl_xor_sync(0xFFFFFFFF, mx1, 2));
        if (t == 0) {
            g_pmax[ra * 32 + blockIdx.y * 2 + wc]       = mx0;
            g_pmax[(ra + 8) * 32 + blockIdx.y * 2 + wc] = mx1;
        }
    }
}

// ===========================================================================
// Fused softmax + PV (fp16 HMMA, cp.async pipeline) — unchanged from R11
// ===========================================================================
#define TSF 68
#define PSTR 36
#define PV_OFF_PS (2 * 128 * TSF)
#define PV_OFF_GS (PV_OFF_PS + 128 * PSTR)
#define PV_OFF_ST (PV_OFF_GS + 128 * PSTR)
#define PV_SMEM_FLOATS (PV_OFF_ST + 2 * 128)

__global__ __launch_bounds__(256, 2) void pv_kernel()
{
    extern __shared__ float sm[];
    uint32_t* Ps  = (uint32_t*)(sm + PV_OFF_PS);
    uint32_t* Gs  = (uint32_t*)(sm + PV_OFF_GS);
    float*   rowm = sm + PV_OFF_ST;
    float*   rowl = rowm + 128;

    int tid = threadIdx.x;
    int b = blockIdx.y, q0 = blockIdx.x * 128;
    const float*  Sp  = g_S + (size_t)(b * NN + q0) * NM;
    const __half* GpH = g_gPt + (size_t)b * ND * NM;

    int lane = tid & 31, g = lane >> 2, t = lane & 3;
    int wid = tid >> 5, wr = wid >> 1, wc = wid & 1;
    int r0 = wr * 32, c0 = wc * 64;

    uint32_t sbase = smem_u32(sm);
    int cr = tid >> 4, cc = (tid & 15) * 4;

    if (tid < 128) {
        const float* pm = g_pmax + (size_t)(b * NN + q0 + tid) * 32;
        float mx = pm[0];
#pragma unroll
        for (int j = 1; j < 32; j++) mx = fmaxf(mx, pm[j]);
        rowm[tid] = mx;
        rowl[tid] = 0.f;
    }

#pragma unroll
    for (int q = 0; q < 4; q++) {
        int idx = q * 256 + tid, r = idx >> 3, hs = (idx & 7) * 8;
        cp_async16(sbase + (PV_OFF_GS + r * PSTR) * 4 + hs * 2, GpH + (size_t)r * NM + hs);
    }
#pragma unroll
    for (int q = 0; q < 8; q++) {
        int r = q * 16 + cr;
        cp_async16(sbase + (r * TSF + cc) * 4, Sp + (size_t)r * NM + cc);
    }
    CP_COMMIT();
#pragma unroll
    for (int q = 0; q < 8; q++) {
        int r = q * 16 + cr;
        cp_async16(sbase + (128 * TSF + r * TSF + cc) * 4, Sp + (size_t)r * NM + 64 + cc);
    }
    CP_COMMIT();

    float yacc[2][8][4];
#pragma unroll
    for (int mt = 0; mt < 2; mt++)
#pragma unroll
        for (int nt = 0; nt < 8; nt++)
#pragma unroll
            for (int i = 0; i < 4; i++) yacc[mt][nt][i] = 0.f;

    int erow = tid >> 1, ecol = (tid & 1) * 32;

#pragma unroll 1
    for (int ch = 0; ch < 32; ch++) {
        int cur = ch & 1;
        float* Ss = sm + cur * 128 * TSF;

        CP_WAIT1();
        __syncthreads();

        {
            float nm = rowm[erow];
            const float* src = Ss + erow * TSF + ecol;
            uint32_t* dst = Ps + erow * PSTR + (ecol >> 1);
            float sum = 0.f;
#pragma unroll
            for (int j = 0; j < 8; j++) {
                float4 v = *(const float4*)(src + j * 4);
                float p0 = __expf(v.x - nm), p1 = __expf(v.y - nm);
                float p2 = __expf(v.z - nm), p3 = __expf(v.w - nm);
                sum += p0 + p1 + p2 + p3;
                __half2 h01 = __floats2half2_rn(p0, p1);
                __half2 h23 = __floats2half2_rn(p2, p3);
                dst[j * 2]     = *(uint32_t*)&h01;
                dst[j * 2 + 1] = *(uint32_t*)&h23;
            }
            sum += __shfl_xor_sync(0xFFFFFFFF, sum, 1);
            if ((tid & 1) == 0) rowl[erow] += sum;
        }
        __syncthreads();

        if (ch + 2 < 32) {
            int m2 = (ch + 2) * 64;
#pragma unroll
            for (int q = 0; q < 8; q++) {
                int r = q * 16 + cr;
                cp_async16(sbase + (cur * 128 * TSF + r * TSF + cc) * 4,
                           Sp + (size_t)r * NM + m2 + cc);
            }
        }

#pragma unroll
        for (int kst = 0; kst < 4; kst++) {
            int kh = kst * 8;
            uint32_t a[2][4];
#pragma unroll
            for (int mt = 0; mt < 2; mt++) {
                const uint32_t* ab = Ps + (r0 + 16 * mt + g) * PSTR + kh + t;
                a[mt][0] = ab[0];
                a[mt][1] = ab[8 * PSTR];
                a[mt][2] = ab[4];
                a[mt][3] = ab[8 * PSTR + 4];
            }
#pragma unroll
            for (int nt = 0; nt < 8; nt++) {
                const uint32_t* gb = Gs + (c0 + 8 * nt + g) * PSTR + kh + t;
                uint32_t b0 = gb[0], b1 = gb[4];
#pragma unroll
                for (int mt = 0; mt < 2; mt++)
                    mma_f16(yacc[mt][nt], a[mt][0], a[mt][1], a[mt][2], a[mt][3], b0, b1);
            }
        }
        __syncthreads();

        if (ch + 1 < 32) {
            int m1 = (ch + 1) * 64;
#pragma unroll
            for (int q = 0; q < 4; q++) {
                int idx = q * 256 + tid, r = idx >> 3, hs = (idx & 7) * 8;
                cp_async16(sbase + (PV_OFF_GS + r * PSTR) * 4 + hs * 2,
                           GpH + (size_t)r * NM + m1 + hs);
            }
        }
        CP_COMMIT();
        CP_COMMIT();
    }

    __syncthreads();
#pragma unroll
    for (int mt = 0; mt < 2; mt++) {
        int ra = r0 + 16 * mt + g, rb = ra + 8;
        float ia = 1.f / rowl[ra], ib = 1.f / rowl[rb];
        float* Y0 = g_y + (size_t)(b * NN + q0 + ra) * ND + c0;
        float* Y1 = g_y + (size_t)(b * NN + q0 + rb) * ND + c0;
#pragma unroll
        for (int nt = 0; nt < 8; nt++) {
            *(float2*)(Y0 + 8 * nt + 2 * t) = make_float2(yacc[mt][nt][0] * ia, yacc[mt][nt][1] * ia);
            *(float2*)(Y1 + 8 * nt + 2 * t) = make_float2(yacc[mt][nt][2] * ib, yacc[mt][nt][3] * ib);
        }
    }
}

// ===========================================================================
// Output GEMM + residual (split-fp16): out = x + y @ Wout
// ===========================================================================
__global__ __launch_bounds__(256, 2) void out_kernel(
    const float* __restrict__ x, const float* __restrict__ Wout, float* __restrict__ out)
{
    extern __shared__ uint32_t smu[];

    int tid = threadIdx.x, row0 = blockIdx.x * 128, col0 = blockIdx.y * 128;
    int lane = tid & 31, g = lane >> 2, t = lane & 3;
    int wid = tid >> 5, wr = wid >> 1, wc = wid & 1;
    int r0 = wr * 32, c0 = wc * 64;

    float acc[2][8][4];
#pragma unroll
    for (int mt = 0; mt < 2; mt++)
#pragma unroll
        for (int nt = 0; nt < 8; nt++)
#pragma unroll
            for (int i = 0; i < 4; i++) acc[mt][nt][i] = 0.f;

#pragma unroll 1
    for (int kc = 0; kc < 2; kc++) {
        int k0 = kc * 64;
        __syncthreads();
#pragma unroll
        for (int q = 0; q < 8; q++) {
            int li = q * 256 + tid, r = li >> 4, c = (li & 15) * 4;
            float4 v = *(const float4*)(g_y + (size_t)(row0 + r) * ND + k0 + c);
            uint2 hi, lo; split4(v, hi, lo);
            *(uint2*)&smu[OFF_AH + r * W36 + (c >> 1)] = hi;
            *(uint2*)&smu[OFF_AL + r * W36 + (c >> 1)] = lo;
        }
#pragma unroll
        for (int q = 0; q < 8; q++) {
            int li = q * 256 + tid, n = li & 127, kq = li >> 7;
            float4 v;
            v.x = Wout[(size_t)(k0 + kq * 4 + 0) * NC + col0 + n];
            v.y = Wout[(size_t)(k0 + kq * 4 + 1) * NC + col0 + n];
            v.z = Wout[(size_t)(k0 + kq * 4 + 2) * NC + col0 + n];
            v.w = Wout[(size_t)(k0 + kq * 4 + 3) * NC + col0 + n];
            uint2 hi, lo; split4(v, hi, lo);
            *(uint2*)&smu[OFF_BH + n * W36 + kq * 2] = hi;
            *(uint2*)&smu[OFF_BL + n * W36 + kq * 2] = lo;
        }
        __syncthreads();
        GEMM_MAINLOOP(smu)
    }
#pragma unroll
    for (int mt = 0; mt < 2; mt++) {
        int ra = row0 + r0 + 16 * mt + g;
        const float* X0 = x + (size_t)ra * NC + col0 + c0;
        const float* X1 = X0 + 8 * (size_t)NC;
        float* O0 = out + (size_t)ra * NC + col0 + c0;
        float* O1 = O0 + 8 * (size_t)NC;
#pragma unroll
        for (int nt = 0; nt < 8; nt++) {
            int cc = 8 * nt + 2 * t;
            float2 x0 = *(const float2*)(X0 + cc);
            float2 x1 = *(const float2*)(X1 + cc);
            *(float2*)(O0 + cc) = make_float2(acc[mt][nt][0] + x0.x, acc[mt][nt][1] + x0.y);
            *(float2*)(O1 + cc) = make_float2(acc[mt][nt][2] + x1.x, acc[mt][nt][3] + x1.y);
        }
    }
}

// ---------------------------------------------------------------------------
extern "C" void kernel_launch(void* const* d_in, const int* in_sizes, int n_in,
                              void* d_out, int out_size)
{
    const float* x  = (const float*)d_in[0];
    const float* Wt = (const float*)d_in[1];
    const float* Wp = (const float*)d_in[2];
    const float* Wg = (const float*)d_in[3];
    const float* Wo = (const float*)d_in[4];
    float* out      = (float*)d_out;

    const int GEMM_SMEM = GEMM_SMEM_U32 * 4;     // 73728 B... (u32 count * 4)
    const int PV_SMEM   = PV_SMEM_FLOATS * 4;    // 107520 B
    cudaFuncSetAttribute(proj_kernel, cudaFuncAttributeMaxDynamicSharedMemorySize, GEMM_SMEM);
    cudaFuncSetAttribute(qk_kernel,   cudaFuncAttributeMaxDynamicSharedMemorySize, GEMM_SMEM);
    cudaFuncSetAttribute(pv_kernel,   cudaFuncAttributeMaxDynamicSharedMemorySize, PV_SMEM);
    cudaFuncSetAttribute(out_kernel,  cudaFuncAttributeMaxDynamicSharedMemorySize, GEMM_SMEM);

    proj_kernel<<<dim3(256, 1, 3), 256, GEMM_SMEM>>>(x, Wt, Wp, Wg);
    pool_kernel<<<(NB * NM * ND / 4 + 255) / 256, 256>>>();
    qk_kernel<<<dim3(32, 16, 8), 256, GEMM_SMEM>>>();
    pv_kernel<<<dim3(32, 8), 256, PV_SMEM>>>();
    out_kernel<<<dim3(256, 2), 256, GEMM_SMEM>>>(x, Wo, out);
}